// round 13
// baseline (speedup 1.0000x reference)
#include <cuda_runtime.h>
#include <cuda_fp16.h>
#include <cstdint>

#define BATCH 4
#define CDIM  256
#define NPIX  4096
typedef __half fp16;

#define CN ((size_t)BATCH * NPIX * CDIM)      // 4,194,304
#define NN ((size_t)BATCH * NPIX * NPIX)      // 67,108,864
#define NSM_CTAS 296                          // 148 SMs x 2 CTAs

// ---------------------------------------------------------------------------
// Device scratch
// ---------------------------------------------------------------------------
__device__ fp16  g_FcT_h[CN], g_FcT_l[CN];    // F_c transposed [b][p][c]
__device__ fp16  g_FsT_h[CN], g_FsT_l[CN];
__device__ fp16  g_wf_h[CDIM*CDIM], g_wf_l[CDIM*CDIM];
__device__ fp16  g_wg_h[CDIM*CDIM], g_wg_l[CDIM*CDIM];
__device__ fp16  g_wh_h[CDIM*CDIM], g_wh_l[CDIM*CDIM];
__device__ fp16  g_wo_h[CDIM*CDIM], g_wo_l[CDIM*CDIM];
__device__ fp16  g_Fq_h[CN], g_Fq_l[CN];      // [b][i][c]
__device__ fp16  g_G_h [CN], g_G_l [CN];      // [b][j][c]
__device__ fp16  g_Hv_h[CN];                  // [b][c][j]
__device__ fp16  g_R_h [CN];                  // [b][i][c]
__device__ fp16  g_E[NN];                     // E = exp(S - m_tile), fp16
__device__ float g_stM[(size_t)BATCH * 32 * NPIX];
__device__ float g_stS[(size_t)BATCH * 32 * NPIX];
__device__ float g_rowM[(size_t)BATCH * NPIX];
__device__ float g_rowIL[(size_t)BATCH * NPIX];

// ---------------------------------------------------------------------------
// PTX helpers (sm_80-level only)
// ---------------------------------------------------------------------------
__device__ __forceinline__ uint32_t smem_u32(const void* p) {
    uint32_t a;
    asm("{ .reg .u64 t; cvta.to.shared.u64 t, %1; cvt.u32.u64 %0, t; }" : "=r"(a) : "l"(p));
    return a;
}
#define CPA(s, g) asm volatile("cp.async.cg.shared.global [%0], [%1], 16;" :: "r"(s), "l"(g) : "memory")
#define CPC()     asm volatile("cp.async.commit_group;" ::: "memory")
#define CPW(n)    asm volatile("cp.async.wait_group %0;" :: "n"(n) : "memory")

__device__ __forceinline__ void ldsm4(uint32_t* r, uint32_t a) {
    asm volatile("ldmatrix.sync.aligned.m8n8.x4.shared.b16 {%0,%1,%2,%3}, [%4];"
        : "=r"(r[0]), "=r"(r[1]), "=r"(r[2]), "=r"(r[3]) : "r"(a));
}
__device__ __forceinline__ void ldsm2(uint32_t* r, uint32_t a) {
    asm volatile("ldmatrix.sync.aligned.m8n8.x2.shared.b16 {%0,%1}, [%2];"
        : "=r"(r[0]), "=r"(r[1]) : "r"(a));
}
__device__ __forceinline__ void mma_fp16(float* c, const uint32_t* a, const uint32_t* b) {
    asm volatile("mma.sync.aligned.m16n8k16.row.col.f32.f16.f16.f32 "
        "{%0,%1,%2,%3}, {%4,%5,%6,%7}, {%8,%9}, {%0,%1,%2,%3};"
        : "+f"(c[0]), "+f"(c[1]), "+f"(c[2]), "+f"(c[3])
        : "r"(a[0]), "r"(a[1]), "r"(a[2]), "r"(a[3]), "r"(b[0]), "r"(b[1]));
}
__device__ __forceinline__ void split2h(float x, fp16& h, fp16& l) {
    h = __float2half_rn(x);
    l = __float2half_rn(x - __half2float(h));
}

#define RSB      80
#define TILE_SB  (128 * RSB)     // 10240
#define STAGE_SB (4 * TILE_SB)   // 40960
#define SF_SB    (128 * 80)      // fp16 E staging
#define DSMEM    (2 * STAGE_SB)            // 81920
#define DSMEM_F  (2 * STAGE_SB + SF_SB)    // 92160

// ===========================================================================
// Persistent merged conv GEMM: 768 tiles (32 x, 2 y, 12 z).
// z<4 -> Fq (3-pass, EPI2); z<8 -> G (3-pass, EPI2); z>=8 -> Hv (2-pass, EPI1)
// ===========================================================================
__global__ void __launch_bounds__(256, 2)
conv_merged(const fp16* __restrict__ wfh, const fp16* __restrict__ wfl,
            const fp16* __restrict__ wgh, const fp16* __restrict__ wgl,
            const fp16* __restrict__ whh, const fp16* __restrict__ whl,
            const fp16* __restrict__ FcTh, const fp16* __restrict__ FcTl,
            const fp16* __restrict__ FsTh, const fp16* __restrict__ FsTl,
            const float* __restrict__ b_f, const float* __restrict__ b_g,
            const float* __restrict__ b_h,
            fp16* __restrict__ Fqh, fp16* __restrict__ Fql,
            fp16* __restrict__ Gh,  fp16* __restrict__ Gl,
            fp16* __restrict__ Hvh)
{
    extern __shared__ char smem[];
    const uint32_t sb = smem_u32(smem);
    const int tid = threadIdx.x;
    const int lane = tid & 31, wid = tid >> 5;
    const int wm = wid >> 2, wn = wid & 3;
    const size_t cn = (size_t)NPIX * CDIM;
    const int nk = CDIM / 32;
    const int r0 = tid >> 2, c0 = tid & 3, r1 = r0 + 64;
    const int aRow = lane & 15, aKB = (lane >> 4) * 16;
    const int bRow = lane & 7,  bKB = ((lane >> 3) & 1) * 16;

    for (int t = blockIdx.x; t < 768; t += gridDim.x) {
        const int zz = t >> 6, rem = t & 63;
        const int m0 = (rem >> 5) * 128, n0 = (rem & 31) * 128;
        const int grp = zz >> 2, b = zz & 3;
        const fp16 *Ah, *Al, *Bh, *Bl;
        const float* bias;
        fp16 *oH, *oL;
        if (grp == 0) {
            Ah = wfh; Al = wfl; Bh = FcTh + b * cn; Bl = FcTl + b * cn;
            bias = b_f; oH = Fqh + b * cn; oL = Fql + b * cn;
        } else if (grp == 1) {
            Ah = wgh; Al = wgl; Bh = FsTh + b * cn; Bl = FsTl + b * cn;
            bias = b_g; oH = Gh + b * cn; oL = Gl + b * cn;
        } else {
            Ah = whh; Al = whl; Bh = FsTh + b * cn; Bl = FsTl + b * cn;
            bias = b_h; oH = Hvh + b * cn; oL = nullptr;
        }
        const bool doP3 = (grp < 2);
        const int epi = (grp < 2) ? 2 : 1;
        const int ldo = (epi == 2) ? CDIM : NPIX;

        auto issue = [&](int kc) {
            if (kc >= nk) return;
            const uint32_t s0 = sb + (uint32_t)(kc & 1) * STAGE_SB;
            const fp16* srcs[4] = {Ah, Al, Bh, Bl};
#pragma unroll
            for (int tt = 0; tt < 4; ++tt) {
                if (tt == 3 && !doP3) continue;
                const fp16* g0 = srcs[tt] + (size_t)(r0 + ((tt < 2) ? m0 : n0)) * CDIM + kc * 32 + c0 * 8;
                const fp16* g1 = srcs[tt] + (size_t)(r1 + ((tt < 2) ? m0 : n0)) * CDIM + kc * 32 + c0 * 8;
                CPA(s0 + tt * TILE_SB + r0 * RSB + c0 * 16, g0);
                CPA(s0 + tt * TILE_SB + r1 * RSB + c0 * 16, g1);
            }
        };

        float acc[4][4][4];
#pragma unroll
        for (int i = 0; i < 4; ++i)
#pragma unroll
            for (int j = 0; j < 4; ++j)
#pragma unroll
                for (int q = 0; q < 4; ++q) acc[i][j][q] = 0.f;

        issue(0); CPC();
        issue(1); CPC();

        for (int kc = 0; kc < nk; ++kc) {
            CPW(1);
            __syncthreads();
            const uint32_t s0 = sb + (uint32_t)(kc & 1) * STAGE_SB;
            const uint32_t aH = s0, aL = s0 + TILE_SB;
            const uint32_t bH = s0 + 2 * TILE_SB, bL = s0 + 3 * TILE_SB;
#pragma unroll
            for (int ks = 0; ks < 2; ++ks) {
                uint32_t Af[2][4][4];
#pragma unroll
                for (int i = 0; i < 4; ++i) {
                    const uint32_t off = (uint32_t)(wm * 64 + i * 16 + aRow) * RSB + ks * 32 + aKB;
                    ldsm4(Af[0][i], aH + off);
                    ldsm4(Af[1][i], aL + off);
                }
#pragma unroll
                for (int jp = 0; jp < 2; ++jp) {
                    uint32_t Bf[2][2][2];
#pragma unroll
                    for (int jj = 0; jj < 2; ++jj) {
                        const int j = jp * 2 + jj;
                        const uint32_t off = (uint32_t)(wn * 32 + j * 8 + bRow) * RSB + ks * 32 + bKB;
                        ldsm2(Bf[0][jj], bH + off);
                        if (doP3) ldsm2(Bf[1][jj], bL + off);
                    }
#pragma unroll
                    for (int jj = 0; jj < 2; ++jj)
#pragma unroll
                        for (int i = 0; i < 4; ++i)
                            mma_fp16(acc[i][jp * 2 + jj], Af[0][i], Bf[0][jj]);
#pragma unroll
                    for (int jj = 0; jj < 2; ++jj)
#pragma unroll
                        for (int i = 0; i < 4; ++i)
                            mma_fp16(acc[i][jp * 2 + jj], Af[1][i], Bf[0][jj]);
                    if (doP3)
#pragma unroll
                        for (int jj = 0; jj < 2; ++jj)
#pragma unroll
                            for (int i = 0; i < 4; ++i)
                                mma_fp16(acc[i][jp * 2 + jj], Af[0][i], Bf[1][jj]);
                }
            }
            __syncthreads();
            issue(kc + 2); CPC();
        }

        // epilogue
        float* stg = (float*)smem;
        const int gid = lane >> 2, tig = lane & 3;
#pragma unroll
        for (int i = 0; i < 4; ++i) {
            const int ml = wm * 64 + i * 16 + gid;
            const float bv0 = bias[m0 + ml];
            const float bv8 = bias[m0 + ml + 8];
#pragma unroll
            for (int j = 0; j < 4; ++j) {
                const int nl = wn * 32 + j * 8 + tig * 2;
                stg[ml * 132 + nl]           = acc[i][j][0] + bv0;
                stg[ml * 132 + nl + 1]       = acc[i][j][1] + bv0;
                stg[(ml + 8) * 132 + nl]     = acc[i][j][2] + bv8;
                stg[(ml + 8) * 132 + nl + 1] = acc[i][j][3] + bv8;
            }
        }
        __syncthreads();

        const int row = tid >> 1, half = tid & 1;
        if (epi == 2) {
            const int n = row, mh = half * 64;
            const size_t base = (size_t)(n0 + n) * ldo + m0 + mh;
#pragma unroll
            for (int v = 0; v < 8; ++v) {
                uint32_t hw[4], lw[4];
#pragma unroll
                for (int q = 0; q < 4; ++q) {
                    float x0 = stg[(mh + v * 8 + q * 2) * 132 + n];
                    float x1 = stg[(mh + v * 8 + q * 2 + 1) * 132 + n];
                    fp16 h0, l0, h1, l1;
                    split2h(x0, h0, l0); split2h(x1, h1, l1);
                    __half2 hp = __halves2half2(h0, h1), lp = __halves2half2(l0, l1);
                    hw[q] = *(uint32_t*)&hp; lw[q] = *(uint32_t*)&lp;
                }
                *(uint4*)(oH + base + v * 8) = make_uint4(hw[0], hw[1], hw[2], hw[3]);
                *(uint4*)(oL + base + v * 8) = make_uint4(lw[0], lw[1], lw[2], lw[3]);
            }
        } else {
            const size_t base = (size_t)(m0 + row) * ldo + n0 + half * 64;
#pragma unroll
            for (int v = 0; v < 8; ++v) {
                uint32_t hw[4];
#pragma unroll
                for (int q = 0; q < 4; ++q) {
                    float x0 = stg[row * 132 + half * 64 + v * 8 + q * 2];
                    float x1 = stg[row * 132 + half * 64 + v * 8 + q * 2 + 1];
                    __half2 hp = __floats2half2_rn(x0, x1);
                    hw[q] = *(uint32_t*)&hp;
                }
                *(uint4*)(oH + base + v * 8) = make_uint4(hw[0], hw[1], hw[2], hw[3]);
            }
        }
        __syncthreads();   // protect stg before next tile's issue(0)
    }
}

// ===========================================================================
// Persistent G4: 4096 tiles (32 n, 32 m, 4 z). 3-pass. Output E + stats.
// ===========================================================================
__global__ void __launch_bounds__(256, 2)
g4_logits(const fp16* __restrict__ Fqh, const fp16* __restrict__ Fql,
          const fp16* __restrict__ Gh,  const fp16* __restrict__ Gl,
          fp16* __restrict__ oE, float* __restrict__ stM, float* __restrict__ stS)
{
    extern __shared__ char smem[];
    const uint32_t sb = smem_u32(smem);
    const int tid = threadIdx.x;
    const int lane = tid & 31, wid = tid >> 5;
    const int wm = wid >> 2, wn = wid & 3;
    const size_t cn = (size_t)NPIX * CDIM;
    const int nk = CDIM / 32;
    const int r0 = tid >> 2, c0 = tid & 3, r1 = r0 + 64;
    const int aRow = lane & 15, aKB = (lane >> 4) * 16;
    const int bRow = lane & 7,  bKB = ((lane >> 3) & 1) * 16;

    for (int t = blockIdx.x; t < 4096; t += gridDim.x) {
        const int z = t >> 10, rem = t & 1023;
        const int mt = rem >> 5, nt = rem & 31;
        const int m0 = mt * 128, n0 = nt * 128;
        const fp16* Ah = Fqh + z * cn;
        const fp16* Al = Fql + z * cn;
        const fp16* Bh = Gh + z * cn;
        const fp16* Bl = Gl + z * cn;

        auto issue = [&](int kc) {
            if (kc >= nk) return;
            const uint32_t s0 = sb + (uint32_t)(kc & 1) * STAGE_SB;
            const fp16* srcs[4] = {Ah, Al, Bh, Bl};
#pragma unroll
            for (int tt = 0; tt < 4; ++tt) {
                const fp16* g0 = srcs[tt] + (size_t)(r0 + ((tt < 2) ? m0 : n0)) * CDIM + kc * 32 + c0 * 8;
                const fp16* g1 = srcs[tt] + (size_t)(r1 + ((tt < 2) ? m0 : n0)) * CDIM + kc * 32 + c0 * 8;
                CPA(s0 + tt * TILE_SB + r0 * RSB + c0 * 16, g0);
                CPA(s0 + tt * TILE_SB + r1 * RSB + c0 * 16, g1);
            }
        };

        float acc[4][4][4];
#pragma unroll
        for (int i = 0; i < 4; ++i)
#pragma unroll
            for (int j = 0; j < 4; ++j)
#pragma unroll
                for (int q = 0; q < 4; ++q) acc[i][j][q] = 0.f;

        issue(0); CPC();
        issue(1); CPC();

        for (int kc = 0; kc < nk; ++kc) {
            CPW(1);
            __syncthreads();
            const uint32_t s0 = sb + (uint32_t)(kc & 1) * STAGE_SB;
            const uint32_t aH = s0, aL = s0 + TILE_SB;
            const uint32_t bH = s0 + 2 * TILE_SB, bL = s0 + 3 * TILE_SB;
#pragma unroll
            for (int ks = 0; ks < 2; ++ks) {
                uint32_t Af[2][4][4];
#pragma unroll
                for (int i = 0; i < 4; ++i) {
                    const uint32_t off = (uint32_t)(wm * 64 + i * 16 + aRow) * RSB + ks * 32 + aKB;
                    ldsm4(Af[0][i], aH + off);
                    ldsm4(Af[1][i], aL + off);
                }
#pragma unroll
                for (int jp = 0; jp < 2; ++jp) {
                    uint32_t Bf[2][2][2];
#pragma unroll
                    for (int jj = 0; jj < 2; ++jj) {
                        const int j = jp * 2 + jj;
                        const uint32_t off = (uint32_t)(wn * 32 + j * 8 + bRow) * RSB + ks * 32 + bKB;
                        ldsm2(Bf[0][jj], bH + off);
                        ldsm2(Bf[1][jj], bL + off);
                    }
#pragma unroll
                    for (int jj = 0; jj < 2; ++jj)
#pragma unroll
                        for (int i = 0; i < 4; ++i)
                            mma_fp16(acc[i][jp * 2 + jj], Af[0][i], Bf[0][jj]);
#pragma unroll
                    for (int jj = 0; jj < 2; ++jj)
#pragma unroll
                        for (int i = 0; i < 4; ++i)
                            mma_fp16(acc[i][jp * 2 + jj], Af[1][i], Bf[0][jj]);
#pragma unroll
                    for (int jj = 0; jj < 2; ++jj)
#pragma unroll
                        for (int i = 0; i < 4; ++i)
                            mma_fp16(acc[i][jp * 2 + jj], Af[0][i], Bf[1][jj]);
                }
            }
            __syncthreads();
            issue(kc + 2); CPC();
        }

        // epilogue: E = exp(D - tile max) + stats
        float* stg = (float*)smem;
        const int gid = lane >> 2, tig = lane & 3;
#pragma unroll
        for (int i = 0; i < 4; ++i) {
            const int ml = wm * 64 + i * 16 + gid;
#pragma unroll
            for (int j = 0; j < 4; ++j) {
                const int nl = wn * 32 + j * 8 + tig * 2;
                stg[ml * 132 + nl]           = acc[i][j][0];
                stg[ml * 132 + nl + 1]       = acc[i][j][1];
                stg[(ml + 8) * 132 + nl]     = acc[i][j][2];
                stg[(ml + 8) * 132 + nl + 1] = acc[i][j][3];
            }
        }
        __syncthreads();

        const int row = tid >> 1, half = tid & 1;
        const size_t base = (size_t)z * ((size_t)NPIX * NPIX) + (size_t)(m0 + row) * NPIX + n0 + half * 64;
        const float* src = &stg[row * 132 + half * 64];
        float mx = -3.0e38f;
#pragma unroll
        for (int q = 0; q < 64; ++q) mx = fmaxf(mx, src[q]);
        mx = fmaxf(mx, __shfl_xor_sync(0xffffffffu, mx, 1));
        float s = 0.f;
#pragma unroll
        for (int v = 0; v < 8; ++v) {
            uint32_t w[4];
#pragma unroll
            for (int q = 0; q < 4; ++q) {
                float e0 = __expf(src[v * 8 + q * 2]     - mx);
                float e1 = __expf(src[v * 8 + q * 2 + 1] - mx);
                s += e0 + e1;
                __half2 hp = __floats2half2_rn(e0, e1);
                w[q] = *(uint32_t*)&hp;
            }
            *(uint4*)(oE + base + v * 8) = make_uint4(w[0], w[1], w[2], w[3]);
        }
        s += __shfl_xor_sync(0xffffffffu, s, 1);
        if (half == 0) {
            size_t o = ((size_t)z * 32 + nt) * NPIX + m0 + row;
            stM[o] = mx; stS[o] = s;
        }
        __syncthreads();
    }
}

// ===========================================================================
// Generic GEMM (R10 loop) for G5 (FUSEB, EPI2) and G6 (EPI0).
// ===========================================================================
template <int EPI, bool FUSEB, int PASSES>
__global__ void __launch_bounds__(256, 2)
mma_gemm(const fp16* __restrict__ Ah_, const fp16* __restrict__ Al_,
         const fp16* __restrict__ Bh_, const fp16* __restrict__ Bl_,
         int K, int lda, int ldb, int ldo,
         long long sA, long long sB, long long sO,
         const float* __restrict__ bias,
         float* __restrict__ outF, fp16* __restrict__ oH, fp16* __restrict__ oL,
         const fp16* __restrict__ Efp, const float* __restrict__ rowM,
         const float* __restrict__ rowIL, const float* __restrict__ stMr)
{
    extern __shared__ char smem[];
    const uint32_t sb = smem_u32(smem);
    const int tid = threadIdx.x;
    const int lane = tid & 31, wid = tid >> 5;
    const int wm = wid >> 2, wn = wid & 3;
    const int z = blockIdx.z;
    const int m0 = blockIdx.y * 128, n0 = blockIdx.x * 128;

    const fp16* pT[4] = {Ah_ + (size_t)z * sA,
                         (PASSES >= 2) ? Al_ + (size_t)z * sA : nullptr,
                         FUSEB ? nullptr : Bh_ + (size_t)z * sB,
                         (!FUSEB && PASSES >= 3) ? Bl_ + (size_t)z * sB : nullptr};
    const int nk = K / 32;
    const int r0 = tid >> 2, c0 = tid & 3, r1 = r0 + 64;

    auto issueA = [&](int kc) {
        if (kc >= nk) return;
        const uint32_t s0 = sb + (uint32_t)(kc & 1) * STAGE_SB;
#pragma unroll
        for (int t = 0; t < 4; ++t) {
            if (t == 1 && PASSES < 2) continue;
            if (t >= 2 && FUSEB) continue;
            if (t == 3 && PASSES < 3) continue;
            const int ld = (t < 2) ? lda : ldb;
            const int base = (t < 2) ? m0 : n0;
            const fp16* g0 = pT[t] + (size_t)(base + r0) * ld + kc * 32 + c0 * 8;
            const fp16* g1 = pT[t] + (size_t)(base + r1) * ld + kc * 32 + c0 * 8;
            CPA(s0 + t * TILE_SB + r0 * RSB + c0 * 16, g0);
            CPA(s0 + t * TILE_SB + r1 * RSB + c0 * 16, g1);
        }
    };

    const int pr = tid >> 1, jh = tid & 1;
    const uint32_t sf = sb + 2 * STAGE_SB;
    float mrow = 0.f, il = 0.f;
    const fp16* Erow = nullptr;
    if (FUSEB) {
        Erow = Efp + (size_t)z * sB + (size_t)(n0 + pr) * ldb;
        mrow = rowM [(size_t)z * NPIX + n0 + pr];
        il   = rowIL[(size_t)z * NPIX + n0 + pr];
    }
    auto issueS = [&](int kc) {
        if (kc >= nk) return;
        const uint32_t d = sf + pr * 80 + jh * 32;
        const fp16* g = Erow + kc * 32 + jh * 16;
        CPA(d, g); CPA(d + 16, g + 8);
    };
    auto convB = [&](int kc) {
        const uint32_t s0 = sb + (kc & 1) * STAGE_SB;
        const int tile = kc >> 2;
        const float st = stMr[((size_t)z * 32 + tile) * NPIX + (n0 + pr)];
        const float scale = __expf(st - mrow) * il;
        const __half2* Ef = (const __half2*)(smem + 2 * STAGE_SB + pr * 80 + jh * 32);
        const uint32_t dH = s0 + 2 * TILE_SB + pr * RSB + jh * 32;
        uint32_t w[8];
#pragma unroll
        for (int q = 0; q < 8; ++q) {
            float2 e = __half22float2(Ef[q]);
            __half2 hp = __floats2half2_rn(e.x * scale, e.y * scale);
            w[q] = *(uint32_t*)&hp;
        }
        asm volatile("st.shared.v4.b32 [%0], {%1,%2,%3,%4};"
            :: "r"(dH), "r"(w[0]), "r"(w[1]), "r"(w[2]), "r"(w[3]) : "memory");
        asm volatile("st.shared.v4.b32 [%0], {%1,%2,%3,%4};"
            :: "r"(dH + 16), "r"(w[4]), "r"(w[5]), "r"(w[6]), "r"(w[7]) : "memory");
    };

    float acc[4][4][4];
#pragma unroll
    for (int i = 0; i < 4; ++i)
#pragma unroll
        for (int j = 0; j < 4; ++j)
#pragma unroll
            for (int q = 0; q < 4; ++q) acc[i][j][q] = 0.f;

    issueA(0); if (FUSEB) issueS(0); CPC();
    issueA(1); CPC();

    const int aRow = lane & 15;
    const int aKB  = (lane >> 4) * 16;
    const int bRow = lane & 7;
    const int bKB  = ((lane >> 3) & 1) * 16;

    for (int kc = 0; kc < nk; ++kc) {
        CPW(1);
        if (FUSEB) convB(kc);
        __syncthreads();
        const uint32_t s0 = sb + (uint32_t)(kc & 1) * STAGE_SB;
        const uint32_t aH = s0, aL = s0 + TILE_SB;
        const uint32_t bH = s0 + 2 * TILE_SB, bL = s0 + 3 * TILE_SB;
#pragma unroll
        for (int ks = 0; ks < 2; ++ks) {
            uint32_t Af[2][4][4];
#pragma unroll
            for (int i = 0; i < 4; ++i) {
                const uint32_t off = (uint32_t)(wm * 64 + i * 16 + aRow) * RSB + ks * 32 + aKB;
                ldsm4(Af[0][i], aH + off);
                if (PASSES >= 2) ldsm4(Af[1][i], aL + off);
            }
#pragma unroll
            for (int jp = 0; jp < 2; ++jp) {
                uint32_t Bf[2][2][2];
#pragma unroll
                for (int jj = 0; jj < 2; ++jj) {
                    const int j = jp * 2 + jj;
                    const uint32_t off = (uint32_t)(wn * 32 + j * 8 + bRow) * RSB + ks * 32 + bKB;
                    ldsm2(Bf[0][jj], bH + off);
                    if (PASSES >= 3) ldsm2(Bf[1][jj], bL + off);
                }
#pragma unroll
                for (int jj = 0; jj < 2; ++jj)
#pragma unroll
                    for (int i = 0; i < 4; ++i)
                        mma_fp16(acc[i][jp * 2 + jj], Af[0][i], Bf[0][jj]);
                if (PASSES >= 2)
#pragma unroll
                    for (int jj = 0; jj < 2; ++jj)
#pragma unroll
                        for (int i = 0; i < 4; ++i)
                            mma_fp16(acc[i][jp * 2 + jj], Af[1][i], Bf[0][jj]);
                if (PASSES >= 3)
#pragma unroll
                    for (int jj = 0; jj < 2; ++jj)
#pragma unroll
                        for (int i = 0; i < 4; ++i)
                            mma_fp16(acc[i][jp * 2 + jj], Af[0][i], Bf[1][jj]);
            }
        }
        __syncthreads();
        if (FUSEB) { issueS(kc + 1); CPC(); issueA(kc + 2); CPC(); }
        else       { issueA(kc + 2); CPC(); }
    }

    // ---- epilogue ----
    float* stg = (float*)smem;
    const int gid = lane >> 2, tig = lane & 3;
#pragma unroll
    for (int i = 0; i < 4; ++i) {
        const int ml = wm * 64 + i * 16 + gid;
        const float bv0 = bias ? bias[m0 + ml] : 0.f;
        const float bv8 = bias ? bias[m0 + ml + 8] : 0.f;
#pragma unroll
        for (int j = 0; j < 4; ++j) {
            const int nl = wn * 32 + j * 8 + tig * 2;
            stg[ml * 132 + nl]           = acc[i][j][0] + bv0;
            stg[ml * 132 + nl + 1]       = acc[i][j][1] + bv0;
            stg[(ml + 8) * 132 + nl]     = acc[i][j][2] + bv8;
            stg[(ml + 8) * 132 + nl + 1] = acc[i][j][3] + bv8;
        }
    }
    __syncthreads();

    const int row = tid >> 1, half = tid & 1;
    if (EPI == 0) {
        float* dst = outF + (size_t)z * sO + (size_t)(m0 + row) * ldo + n0 + half * 64;
        const float4* s4 = (const float4*)&stg[row * 132 + half * 64];
#pragma unroll
        for (int i = 0; i < 16; ++i) ((float4*)dst)[i] = s4[i];
    } else {   // EPI == 2
        const int n = row, mh = half * 64;
        const size_t base = (size_t)z * sO + (size_t)(n0 + n) * ldo + m0 + mh;
#pragma unroll
        for (int v = 0; v < 8; ++v) {
            uint32_t hw[4];
#pragma unroll
            for (int q = 0; q < 4; ++q) {
                float x0 = stg[(mh + v * 8 + q * 2) * 132 + n];
                float x1 = stg[(mh + v * 8 + q * 2 + 1) * 132 + n];
                __half2 hp = __floats2half2_rn(x0, x1);
                hw[q] = *(uint32_t*)&hp;
            }
            *(uint4*)(oH + base + v * 8) = make_uint4(hw[0], hw[1], hw[2], hw[3]);
        }
    }
}

// ---------------------------------------------------------------------------
__global__ void __launch_bounds__(256)
combine_stats(const float* __restrict__ stM, const float* __restrict__ stS,
              float* __restrict__ rowM, float* __restrict__ rowIL)
{
    const int idx = blockIdx.x * 256 + threadIdx.x;
    if (idx >= BATCH * NPIX) return;
    const int z = idx >> 12, i = idx & (NPIX - 1);
    float m = -3.0e38f;
#pragma unroll 4
    for (int t = 0; t < 32; ++t)
        m = fmaxf(m, stM[((size_t)z * 32 + t) * NPIX + i]);
    float l = 0.f;
#pragma unroll 4
    for (int t = 0; t < 32; ++t) {
        size_t o = ((size_t)z * 32 + t) * NPIX + i;
        l += stS[o] * __expf(stM[o] - m);
    }
    rowM[idx] = m;
    rowIL[idx] = 1.0f / l;
}

// ---------------------------------------------------------------------------
__global__ void __launch_bounds__(256)
tsplit_both(const float* __restrict__ Fc, const float* __restrict__ Fs,
            fp16* __restrict__ ohc, fp16* __restrict__ olc,
            fp16* __restrict__ ohs, fp16* __restrict__ ols)
{
    __shared__ float t[32][33];
    const int zz = blockIdx.z;
    const int b = zz & 3;
    const float* X = (zz < 4) ? Fc : Fs;
    fp16* oh = (zz < 4) ? ohc : ohs;
    fp16* ol = (zz < 4) ? olc : ols;
    const int pb = blockIdx.x * 32, cb = blockIdx.y * 32;
    const float* src = X + (size_t)b * CDIM * NPIX;
#pragma unroll
    for (int j = 0; j < 4; ++j) {
        int c = cb + threadIdx.y + j * 8;
        t[threadIdx.y + j * 8][threadIdx.x] = src[(size_t)c * NPIX + pb + threadIdx.x];
    }
    __syncthreads();
#pragma unroll
    for (int j = 0; j < 4; ++j) {
        int p = pb + threadIdx.y + j * 8;
        float v = t[threadIdx.x][threadIdx.y + j * 8];
        size_t o = (size_t)b * NPIX * CDIM + (size_t)p * CDIM + cb + threadIdx.x;
        fp16 h, l; split2h(v, h, l);
        oh[o] = h; ol[o] = l;
    }
}

__global__ void __launch_bounds__(256)
wsplit_all(const float* __restrict__ w0, const float* __restrict__ w1,
           const float* __restrict__ w2, const float* __restrict__ w3,
           fp16* __restrict__ h0, fp16* __restrict__ l0,
           fp16* __restrict__ h1, fp16* __restrict__ l1,
           fp16* __restrict__ h2, fp16* __restrict__ l2,
           fp16* __restrict__ h3, fp16* __restrict__ l3)
{
    const float* w = (blockIdx.y == 0) ? w0 : (blockIdx.y == 1) ? w1 : (blockIdx.y == 2) ? w2 : w3;
    fp16* hh = (blockIdx.y == 0) ? h0 : (blockIdx.y == 1) ? h1 : (blockIdx.y == 2) ? h2 : h3;
    fp16* ll = (blockIdx.y == 0) ? l0 : (blockIdx.y == 1) ? l1 : (blockIdx.y == 2) ? l2 : l3;
    int i = blockIdx.x * 256 + threadIdx.x;
    if (i < CDIM * CDIM) { fp16 a, b; split2h(w[i], a, b); hh[i] = a; ll[i] = b; }
}

// ---------------------------------------------------------------------------
extern "C" void kernel_launch(void* const* d_in, const int* in_sizes, int n_in,
                              void* d_out, int out_size)
{
    const float* F_c = (const float*)d_in[0];
    const float* F_s = (const float*)d_in[1];
    const float* w_f = (const float*)d_in[2];
    const float* b_f = (const float*)d_in[3];
    const float* w_g = (const float*)d_in[4];
    const float* b_g = (const float*)d_in[5];
    const float* w_h = (const float*)d_in[6];
    const float* b_h = (const float*)d_in[7];
    const float* w_o = (const float*)d_in[8];
    const float* b_o = (const float*)d_in[9];
    float* out = (float*)d_out;

    fp16 *FcTh, *FcTl, *FsTh, *FsTl, *wfh, *wfl, *wgh, *wgl, *whh, *whl, *woh, *wol;
    fp16 *Fqh, *Fql, *Gh, *Gl, *Hvh, *Rh, *E;
    float *stM, *stS, *rowM, *rowIL;
    cudaGetSymbolAddress((void**)&FcTh, g_FcT_h); cudaGetSymbolAddress((void**)&FcTl, g_FcT_l);
    cudaGetSymbolAddress((void**)&FsTh, g_FsT_h); cudaGetSymbolAddress((void**)&FsTl, g_FsT_l);
    cudaGetSymbolAddress((void**)&wfh, g_wf_h);   cudaGetSymbolAddress((void**)&wfl, g_wf_l);
    cudaGetSymbolAddress((void**)&wgh, g_wg_h);   cudaGetSymbolAddress((void**)&wgl, g_wg_l);
    cudaGetSymbolAddress((void**)&whh, g_wh_h);   cudaGetSymbolAddress((void**)&whl, g_wh_l);
    cudaGetSymbolAddress((void**)&woh, g_wo_h);   cudaGetSymbolAddress((void**)&wol, g_wo_l);
    cudaGetSymbolAddress((void**)&Fqh, g_Fq_h);   cudaGetSymbolAddress((void**)&Fql, g_Fq_l);
    cudaGetSymbolAddress((void**)&Gh,  g_G_h);    cudaGetSymbolAddress((void**)&Gl,  g_G_l);
    cudaGetSymbolAddress((void**)&Hvh, g_Hv_h);   cudaGetSymbolAddress((void**)&Rh,  g_R_h);
    cudaGetSymbolAddress((void**)&E,   g_E);
    cudaGetSymbolAddress((void**)&stM, g_stM);    cudaGetSymbolAddress((void**)&stS, g_stS);
    cudaGetSymbolAddress((void**)&rowM, g_rowM);  cudaGetSymbolAddress((void**)&rowIL, g_rowIL);

    cudaFuncSetAttribute((const void*)conv_merged, cudaFuncAttributeMaxDynamicSharedMemorySize, DSMEM);
    cudaFuncSetAttribute((const void*)g4_logits, cudaFuncAttributeMaxDynamicSharedMemorySize, DSMEM);
    cudaFuncSetAttribute((const void*)mma_gemm<2,true ,1>, cudaFuncAttributeMaxDynamicSharedMemorySize, DSMEM_F);
    cudaFuncSetAttribute((const void*)mma_gemm<0,false,2>, cudaFuncAttributeMaxDynamicSharedMemorySize, DSMEM);

    const long long cn = (long long)NPIX * CDIM;
    const long long nn = (long long)NPIX * NPIX;

    dim3 gConv(NPIX / 128, CDIM / 128, BATCH);   // 32 x 2 x 4 = 256

    // L1, L2: conversions
    wsplit_all<<<dim3(256, 4), 256>>>(w_f, w_g, w_h, w_o,
        wfh, wfl, wgh, wgl, whh, whl, woh, wol);
    tsplit_both<<<dim3(128, 8, 8), dim3(32, 8)>>>(F_c, F_s, FcTh, FcTl, FsTh, FsTl);
    // L3: persistent merged G1+G2+G3
    conv_merged<<<NSM_CTAS, 256, DSMEM>>>(wfh, wfl, wgh, wgl, whh, whl,
        FcTh, FcTl, FsTh, FsTl, b_f, b_g, b_h, Fqh, Fql, Gh, Gl, Hvh);
    // L4: persistent G4 (E + stats)
    g4_logits<<<NSM_CTAS, 256, DSMEM>>>(Fqh, Fql, Gh, Gl, E, stM, stS);
    // L5: stats fold
    combine_stats<<<(BATCH * NPIX + 255) / 256, 256>>>(stM, stS, rowM, rowIL);
    // L6 (G5): R_t hi only (1-pass, FUSEB)
    mma_gemm<2,true,1><<<gConv, 256, DSMEM_F>>>(Hvh, nullptr, nullptr, nullptr,
        NPIX, NPIX, NPIX, CDIM, cn, nn, cn, nullptr, nullptr, Rh, nullptr,
        E, rowM, rowIL, stM);
    // L7 (G6): out = w_o @ R + b_o (2-pass)
    mma_gemm<0,false,2><<<gConv, 256, DSMEM>>>(woh, wol, Rh, nullptr,
        CDIM, CDIM, CDIM, NPIX, 0, cn, cn, b_o, out, nullptr, nullptr,
        nullptr, nullptr, nullptr, nullptr);
}

// round 14
// speedup vs baseline: 1.0474x; 1.0474x over previous
#include <cuda_runtime.h>
#include <cuda_fp16.h>
#include <cstdint>

#define BATCH 4
#define CDIM  256
#define NPIX  4096
typedef __half fp16;

#define CN ((size_t)BATCH * NPIX * CDIM)      // 4,194,304
#define NN ((size_t)BATCH * NPIX * NPIX)      // 67,108,864

// ---------------------------------------------------------------------------
// Device scratch
// ---------------------------------------------------------------------------
__device__ fp16  g_FcT_h[CN], g_FcT_l[CN];    // F_c transposed [b][p][c]
__device__ fp16  g_FsT_h[CN], g_FsT_l[CN];
__device__ fp16  g_wf_h[CDIM*CDIM], g_wf_l[CDIM*CDIM];
__device__ fp16  g_wg_h[CDIM*CDIM], g_wg_l[CDIM*CDIM];
__device__ fp16  g_wh_h[CDIM*CDIM], g_wh_l[CDIM*CDIM];
__device__ fp16  g_wo_h[CDIM*CDIM], g_wo_l[CDIM*CDIM];
__device__ fp16  g_Fq_h[CN], g_Fq_l[CN];      // [b][i][c]
__device__ fp16  g_G_h [CN], g_G_l [CN];      // [b][j][c]
__device__ fp16  g_Hv_h[CN];                  // [b][c][j]
__device__ fp16  g_R_h [CN];                  // [b][i][c]
__device__ fp16  g_E[NN];                     // E = exp(S - m_tile), fp16
__device__ float g_stM[(size_t)BATCH * 32 * NPIX];
__device__ float g_stS[(size_t)BATCH * 32 * NPIX];
__device__ float g_rowM[(size_t)BATCH * NPIX];
__device__ float g_rowIL[(size_t)BATCH * NPIX];

// ---------------------------------------------------------------------------
// PTX helpers (sm_80-level only)
// ---------------------------------------------------------------------------
__device__ __forceinline__ uint32_t smem_u32(const void* p) {
    uint32_t a;
    asm("{ .reg .u64 t; cvta.to.shared.u64 t, %1; cvt.u32.u64 %0, t; }" : "=r"(a) : "l"(p));
    return a;
}
#define CPA(s, g) asm volatile("cp.async.cg.shared.global [%0], [%1], 16;" :: "r"(s), "l"(g) : "memory")
#define CPC()     asm volatile("cp.async.commit_group;" ::: "memory")
#define CPW(n)    asm volatile("cp.async.wait_group %0;" :: "n"(n) : "memory")

__device__ __forceinline__ void ldsm4(uint32_t* r, uint32_t a) {
    asm volatile("ldmatrix.sync.aligned.m8n8.x4.shared.b16 {%0,%1,%2,%3}, [%4];"
        : "=r"(r[0]), "=r"(r[1]), "=r"(r[2]), "=r"(r[3]) : "r"(a));
}
__device__ __forceinline__ void ldsm2(uint32_t* r, uint32_t a) {
    asm volatile("ldmatrix.sync.aligned.m8n8.x2.shared.b16 {%0,%1}, [%2];"
        : "=r"(r[0]), "=r"(r[1]) : "r"(a));
}
__device__ __forceinline__ void mma_fp16(float* c, const uint32_t* a, const uint32_t* b) {
    asm volatile("mma.sync.aligned.m16n8k16.row.col.f32.f16.f16.f32 "
        "{%0,%1,%2,%3}, {%4,%5,%6,%7}, {%8,%9}, {%0,%1,%2,%3};"
        : "+f"(c[0]), "+f"(c[1]), "+f"(c[2]), "+f"(c[3])
        : "r"(a[0]), "r"(a[1]), "r"(a[2]), "r"(a[3]), "r"(b[0]), "r"(b[1]));
}
__device__ __forceinline__ void split2h(float x, fp16& h, fp16& l) {
    h = __float2half_rn(x);
    l = __float2half_rn(x - __half2float(h));
}

#define RSB      80
#define TILE_SB  (128 * RSB)     // 10240
#define STAGE_SB (4 * TILE_SB)   // 40960
#define SF_SB    (128 * 80)      // fp16 E staging
#define DSMEM    (2 * STAGE_SB)            // 81920
#define DSMEM_F  (2 * STAGE_SB + SF_SB)    // 92160

// ===========================================================================
// Merged conv GEMM (R12 launch shape): grid (32, 2, 12).
// z<4 -> Fq (3-pass, EPI2); z<8 -> G (3-pass, EPI2); z>=8 -> Hv (2-pass, EPI1)
// ===========================================================================
__global__ void __launch_bounds__(256, 2)
conv_merged(const fp16* __restrict__ wfh, const fp16* __restrict__ wfl,
            const fp16* __restrict__ wgh, const fp16* __restrict__ wgl,
            const fp16* __restrict__ whh, const fp16* __restrict__ whl,
            const fp16* __restrict__ FcTh, const fp16* __restrict__ FcTl,
            const fp16* __restrict__ FsTh, const fp16* __restrict__ FsTl,
            const float* __restrict__ b_f, const float* __restrict__ b_g,
            const float* __restrict__ b_h,
            fp16* __restrict__ Fqh, fp16* __restrict__ Fql,
            fp16* __restrict__ Gh,  fp16* __restrict__ Gl,
            fp16* __restrict__ Hvh)
{
    extern __shared__ char smem[];
    const uint32_t sb = smem_u32(smem);
    const int tid = threadIdx.x;
    const int lane = tid & 31, wid = tid >> 5;
    const int wm = wid >> 2, wn = wid & 3;
    const int m0 = blockIdx.y * 128, n0 = blockIdx.x * 128;

    const int zz = blockIdx.z, grp = zz >> 2, b = zz & 3;
    const size_t cn = (size_t)NPIX * CDIM;
    const fp16 *Ah, *Al, *Bh, *Bl;
    const float* bias;
    fp16 *oH, *oL;
    if (grp == 0) {
        Ah = wfh; Al = wfl; Bh = FcTh + b * cn; Bl = FcTl + b * cn;
        bias = b_f; oH = Fqh + b * cn; oL = Fql + b * cn;
    } else if (grp == 1) {
        Ah = wgh; Al = wgl; Bh = FsTh + b * cn; Bl = FsTl + b * cn;
        bias = b_g; oH = Gh + b * cn; oL = Gl + b * cn;
    } else {
        Ah = whh; Al = whl; Bh = FsTh + b * cn; Bl = FsTl + b * cn;
        bias = b_h; oH = Hvh + b * cn; oL = nullptr;
    }
    const bool doP3 = (grp < 2);
    const int epi = (grp < 2) ? 2 : 1;
    const int ldo = (epi == 2) ? CDIM : NPIX;

    const int nk = CDIM / 32;   // 8
    const int r0 = tid >> 2, c0 = tid & 3, r1 = r0 + 64;

    auto issue = [&](int kc) {
        if (kc >= nk) return;
        const uint32_t s0 = sb + (uint32_t)(kc & 1) * STAGE_SB;
        const fp16* srcs[4] = {Ah, Al, Bh, Bl};
#pragma unroll
        for (int t = 0; t < 4; ++t) {
            if (t == 3 && !doP3) continue;
            const fp16* g0 = srcs[t] + (size_t)(r0 + ((t < 2) ? m0 : n0)) * CDIM + kc * 32 + c0 * 8;
            const fp16* g1 = srcs[t] + (size_t)(r1 + ((t < 2) ? m0 : n0)) * CDIM + kc * 32 + c0 * 8;
            CPA(s0 + t * TILE_SB + r0 * RSB + c0 * 16, g0);
            CPA(s0 + t * TILE_SB + r1 * RSB + c0 * 16, g1);
        }
    };

    float acc[4][4][4];
#pragma unroll
    for (int i = 0; i < 4; ++i)
#pragma unroll
        for (int j = 0; j < 4; ++j)
#pragma unroll
            for (int q = 0; q < 4; ++q) acc[i][j][q] = 0.f;

    issue(0); CPC();
    issue(1); CPC();

    const int aRow = lane & 15;
    const int aKB  = (lane >> 4) * 16;
    const int bRow = lane & 7;
    const int bKB  = ((lane >> 3) & 1) * 16;

    for (int kc = 0; kc < nk; ++kc) {
        CPW(1);
        __syncthreads();
        const uint32_t s0 = sb + (uint32_t)(kc & 1) * STAGE_SB;
        const uint32_t aH = s0, aL = s0 + TILE_SB;
        const uint32_t bH = s0 + 2 * TILE_SB, bL = s0 + 3 * TILE_SB;
#pragma unroll
        for (int ks = 0; ks < 2; ++ks) {
            uint32_t Af[2][4][4];
#pragma unroll
            for (int i = 0; i < 4; ++i) {
                const uint32_t off = (uint32_t)(wm * 64 + i * 16 + aRow) * RSB + ks * 32 + aKB;
                ldsm4(Af[0][i], aH + off);
                ldsm4(Af[1][i], aL + off);
            }
#pragma unroll
            for (int jp = 0; jp < 2; ++jp) {
                uint32_t Bf[2][2][2];
#pragma unroll
                for (int jj = 0; jj < 2; ++jj) {
                    const int j = jp * 2 + jj;
                    const uint32_t off = (uint32_t)(wn * 32 + j * 8 + bRow) * RSB + ks * 32 + bKB;
                    ldsm2(Bf[0][jj], bH + off);
                    if (doP3) ldsm2(Bf[1][jj], bL + off);
                }
#pragma unroll
                for (int jj = 0; jj < 2; ++jj)
#pragma unroll
                    for (int i = 0; i < 4; ++i)
                        mma_fp16(acc[i][jp * 2 + jj], Af[0][i], Bf[0][jj]);
#pragma unroll
                for (int jj = 0; jj < 2; ++jj)
#pragma unroll
                    for (int i = 0; i < 4; ++i)
                        mma_fp16(acc[i][jp * 2 + jj], Af[1][i], Bf[0][jj]);
                if (doP3)
#pragma unroll
                    for (int jj = 0; jj < 2; ++jj)
#pragma unroll
                        for (int i = 0; i < 4; ++i)
                            mma_fp16(acc[i][jp * 2 + jj], Af[0][i], Bf[1][jj]);
            }
        }
        __syncthreads();
        issue(kc + 2); CPC();
    }

    // ---- epilogue: stage D (+bias on m) ----
    float* stg = (float*)smem;
    const int gid = lane >> 2, tig = lane & 3;
#pragma unroll
    for (int i = 0; i < 4; ++i) {
        const int ml = wm * 64 + i * 16 + gid;
        const float bv0 = bias[m0 + ml];
        const float bv8 = bias[m0 + ml + 8];
#pragma unroll
        for (int j = 0; j < 4; ++j) {
            const int nl = wn * 32 + j * 8 + tig * 2;
            stg[ml * 132 + nl]           = acc[i][j][0] + bv0;
            stg[ml * 132 + nl + 1]       = acc[i][j][1] + bv0;
            stg[(ml + 8) * 132 + nl]     = acc[i][j][2] + bv8;
            stg[(ml + 8) * 132 + nl + 1] = acc[i][j][3] + bv8;
        }
    }
    __syncthreads();

    const int row = tid >> 1, half = tid & 1;
    if (epi == 2) {
        const int n = row, mh = half * 64;
        const size_t base = (size_t)(n0 + n) * ldo + m0 + mh;
#pragma unroll
        for (int v = 0; v < 8; ++v) {
            uint32_t hw[4], lw[4];
#pragma unroll
            for (int q = 0; q < 4; ++q) {
                float x0 = stg[(mh + v * 8 + q * 2) * 132 + n];
                float x1 = stg[(mh + v * 8 + q * 2 + 1) * 132 + n];
                fp16 h0, l0, h1, l1;
                split2h(x0, h0, l0); split2h(x1, h1, l1);
                __half2 hp = __halves2half2(h0, h1), lp = __halves2half2(l0, l1);
                hw[q] = *(uint32_t*)&hp; lw[q] = *(uint32_t*)&lp;
            }
            *(uint4*)(oH + base + v * 8) = make_uint4(hw[0], hw[1], hw[2], hw[3]);
            *(uint4*)(oL + base + v * 8) = make_uint4(lw[0], lw[1], lw[2], lw[3]);
        }
    } else {
        const size_t base = (size_t)(m0 + row) * ldo + n0 + half * 64;
#pragma unroll
        for (int v = 0; v < 8; ++v) {
            uint32_t hw[4];
#pragma unroll
            for (int q = 0; q < 4; ++q) {
                float x0 = stg[row * 132 + half * 64 + v * 8 + q * 2];
                float x1 = stg[row * 132 + half * 64 + v * 8 + q * 2 + 1];
                __half2 hp = __floats2half2_rn(x0, x1);
                hw[q] = *(uint32_t*)&hp;
            }
            *(uint4*)(oH + base + v * 8) = make_uint4(hw[0], hw[1], hw[2], hw[3]);
        }
    }
}

// ===========================================================================
// Generic GEMM (R12 loop). EPI: 0 fp32(+bias); 2 fp16 transposed (lo opt);
// 3 E=exp(D - tile max) fp16 + stats. FUSEB: B from E * exp(mt-m)*il.
// ===========================================================================
template <int EPI, bool FUSEB, int PASSES>
__global__ void __launch_bounds__(256, 2)
mma_gemm(const fp16* __restrict__ Ah_, const fp16* __restrict__ Al_,
         const fp16* __restrict__ Bh_, const fp16* __restrict__ Bl_,
         int K, int lda, int ldb, int ldo,
         long long sA, long long sB, long long sO,
         const float* __restrict__ bias,
         float* __restrict__ outF, fp16* __restrict__ oH, fp16* __restrict__ oL,
         const fp16* __restrict__ Efp, const float* __restrict__ rowM,
         const float* __restrict__ rowIL, const float* __restrict__ stMr,
         float* __restrict__ stM, float* __restrict__ stS)
{
    extern __shared__ char smem[];
    const uint32_t sb = smem_u32(smem);
    const int tid = threadIdx.x;
    const int lane = tid & 31, wid = tid >> 5;
    const int wm = wid >> 2, wn = wid & 3;
    const int z = blockIdx.z;
    const int m0 = blockIdx.y * 128, n0 = blockIdx.x * 128;

    const fp16* pT[4] = {Ah_ + (size_t)z * sA,
                         (PASSES >= 2) ? Al_ + (size_t)z * sA : nullptr,
                         FUSEB ? nullptr : Bh_ + (size_t)z * sB,
                         (!FUSEB && PASSES >= 3) ? Bl_ + (size_t)z * sB : nullptr};
    const int nk = K / 32;
    const int r0 = tid >> 2, c0 = tid & 3, r1 = r0 + 64;

    auto issueA = [&](int kc) {
        if (kc >= nk) return;
        const uint32_t s0 = sb + (uint32_t)(kc & 1) * STAGE_SB;
#pragma unroll
        for (int t = 0; t < 4; ++t) {
            if (t == 1 && PASSES < 2) continue;
            if (t >= 2 && FUSEB) continue;
            if (t == 3 && PASSES < 3) continue;
            const int ld = (t < 2) ? lda : ldb;
            const int base = (t < 2) ? m0 : n0;
            const fp16* g0 = pT[t] + (size_t)(base + r0) * ld + kc * 32 + c0 * 8;
            const fp16* g1 = pT[t] + (size_t)(base + r1) * ld + kc * 32 + c0 * 8;
            CPA(s0 + t * TILE_SB + r0 * RSB + c0 * 16, g0);
            CPA(s0 + t * TILE_SB + r1 * RSB + c0 * 16, g1);
        }
    };

    const int pr = tid >> 1, jh = tid & 1;
    const uint32_t sf = sb + 2 * STAGE_SB;
    float mrow = 0.f, il = 0.f;
    const fp16* Erow = nullptr;
    if (FUSEB) {
        Erow = Efp + (size_t)z * sB + (size_t)(n0 + pr) * ldb;
        mrow = rowM [(size_t)z * NPIX + n0 + pr];
        il   = rowIL[(size_t)z * NPIX + n0 + pr];
    }
    auto issueS = [&](int kc) {
        if (kc >= nk) return;
        const uint32_t d = sf + pr * 80 + jh * 32;
        const fp16* g = Erow + kc * 32 + jh * 16;
        CPA(d, g); CPA(d + 16, g + 8);
    };
    auto convB = [&](int kc) {
        const uint32_t s0 = sb + (kc & 1) * STAGE_SB;
        const int tile = kc >> 2;
        const float st = stMr[((size_t)z * 32 + tile) * NPIX + (n0 + pr)];
        const float scale = __expf(st - mrow) * il;
        const __half2* Ef = (const __half2*)(smem + 2 * STAGE_SB + pr * 80 + jh * 32);
        const uint32_t dH = s0 + 2 * TILE_SB + pr * RSB + jh * 32;
        uint32_t w[8];
#pragma unroll
        for (int q = 0; q < 8; ++q) {
            float2 e = __half22float2(Ef[q]);
            __half2 hp = __floats2half2_rn(e.x * scale, e.y * scale);
            w[q] = *(uint32_t*)&hp;
        }
        asm volatile("st.shared.v4.b32 [%0], {%1,%2,%3,%4};"
            :: "r"(dH), "r"(w[0]), "r"(w[1]), "r"(w[2]), "r"(w[3]) : "memory");
        asm volatile("st.shared.v4.b32 [%0], {%1,%2,%3,%4};"
            :: "r"(dH + 16), "r"(w[4]), "r"(w[5]), "r"(w[6]), "r"(w[7]) : "memory");
    };

    float acc[4][4][4];
#pragma unroll
    for (int i = 0; i < 4; ++i)
#pragma unroll
        for (int j = 0; j < 4; ++j)
#pragma unroll
            for (int q = 0; q < 4; ++q) acc[i][j][q] = 0.f;

    issueA(0); if (FUSEB) issueS(0); CPC();
    issueA(1); CPC();

    const int aRow = lane & 15;
    const int aKB  = (lane >> 4) * 16;
    const int bRow = lane & 7;
    const int bKB  = ((lane >> 3) & 1) * 16;

    for (int kc = 0; kc < nk; ++kc) {
        CPW(1);
        if (FUSEB) convB(kc);
        __syncthreads();
        const uint32_t s0 = sb + (uint32_t)(kc & 1) * STAGE_SB;
        const uint32_t aH = s0, aL = s0 + TILE_SB;
        const uint32_t bH = s0 + 2 * TILE_SB, bL = s0 + 3 * TILE_SB;
#pragma unroll
        for (int ks = 0; ks < 2; ++ks) {
            uint32_t Af[2][4][4];
#pragma unroll
            for (int i = 0; i < 4; ++i) {
                const uint32_t off = (uint32_t)(wm * 64 + i * 16 + aRow) * RSB + ks * 32 + aKB;
                ldsm4(Af[0][i], aH + off);
                if (PASSES >= 2) ldsm4(Af[1][i], aL + off);
            }
#pragma unroll
            for (int jp = 0; jp < 2; ++jp) {
                uint32_t Bf[2][2][2];
#pragma unroll
                for (int jj = 0; jj < 2; ++jj) {
                    const int j = jp * 2 + jj;
                    const uint32_t off = (uint32_t)(wn * 32 + j * 8 + bRow) * RSB + ks * 32 + bKB;
                    ldsm2(Bf[0][jj], bH + off);
                    if (PASSES >= 3) ldsm2(Bf[1][jj], bL + off);
                }
#pragma unroll
                for (int jj = 0; jj < 2; ++jj)
#pragma unroll
                    for (int i = 0; i < 4; ++i)
                        mma_fp16(acc[i][jp * 2 + jj], Af[0][i], Bf[0][jj]);
                if (PASSES >= 2)
#pragma unroll
                    for (int jj = 0; jj < 2; ++jj)
#pragma unroll
                        for (int i = 0; i < 4; ++i)
                            mma_fp16(acc[i][jp * 2 + jj], Af[1][i], Bf[0][jj]);
                if (PASSES >= 3)
#pragma unroll
                    for (int jj = 0; jj < 2; ++jj)
#pragma unroll
                        for (int i = 0; i < 4; ++i)
                            mma_fp16(acc[i][jp * 2 + jj], Af[0][i], Bf[1][jj]);
            }
        }
        __syncthreads();
        if (FUSEB) { issueS(kc + 1); CPC(); issueA(kc + 2); CPC(); }
        else       { issueA(kc + 2); CPC(); }
    }

    // ---- epilogue ----
    float* stg = (float*)smem;
    const int gid = lane >> 2, tig = lane & 3;
#pragma unroll
    for (int i = 0; i < 4; ++i) {
        const int ml = wm * 64 + i * 16 + gid;
        const float bv0 = bias ? bias[m0 + ml] : 0.f;
        const float bv8 = bias ? bias[m0 + ml + 8] : 0.f;
#pragma unroll
        for (int j = 0; j < 4; ++j) {
            const int nl = wn * 32 + j * 8 + tig * 2;
            stg[ml * 132 + nl]           = acc[i][j][0] + bv0;
            stg[ml * 132 + nl + 1]       = acc[i][j][1] + bv0;
            stg[(ml + 8) * 132 + nl]     = acc[i][j][2] + bv8;
            stg[(ml + 8) * 132 + nl + 1] = acc[i][j][3] + bv8;
        }
    }
    __syncthreads();

    const int row = tid >> 1, half = tid & 1;
    if (EPI == 0) {
        float* dst = outF + (size_t)z * sO + (size_t)(m0 + row) * ldo + n0 + half * 64;
        const float4* s4 = (const float4*)&stg[row * 132 + half * 64];
#pragma unroll
        for (int i = 0; i < 16; ++i) ((float4*)dst)[i] = s4[i];
    } else if (EPI == 2) {
        const int n = row, mh = half * 64;
        const size_t base = (size_t)z * sO + (size_t)(n0 + n) * ldo + m0 + mh;
#pragma unroll
        for (int v = 0; v < 8; ++v) {
            uint32_t hw[4];
#pragma unroll
            for (int q = 0; q < 4; ++q) {
                float x0 = stg[(mh + v * 8 + q * 2) * 132 + n];
                float x1 = stg[(mh + v * 8 + q * 2 + 1) * 132 + n];
                __half2 hp = __floats2half2_rn(x0, x1);
                hw[q] = *(uint32_t*)&hp;
            }
            *(uint4*)(oH + base + v * 8) = make_uint4(hw[0], hw[1], hw[2], hw[3]);
        }
    } else {   // EPI == 3
        const size_t base = (size_t)z * sO + (size_t)(m0 + row) * ldo + n0 + half * 64;
        const float* src = &stg[row * 132 + half * 64];
        float mx = -3.0e38f;
#pragma unroll
        for (int q = 0; q < 64; ++q) mx = fmaxf(mx, src[q]);
        mx = fmaxf(mx, __shfl_xor_sync(0xffffffffu, mx, 1));
        float s = 0.f;
#pragma unroll
        for (int v = 0; v < 8; ++v) {
            uint32_t w[4];
#pragma unroll
            for (int q = 0; q < 4; ++q) {
                float e0 = __expf(src[v * 8 + q * 2]     - mx);
                float e1 = __expf(src[v * 8 + q * 2 + 1] - mx);
                s += e0 + e1;
                __half2 hp = __floats2half2_rn(e0, e1);
                w[q] = *(uint32_t*)&hp;
            }
            *(uint4*)(oH + base + v * 8) = make_uint4(w[0], w[1], w[2], w[3]);
        }
        s += __shfl_xor_sync(0xffffffffu, s, 1);
        if (half == 0) {
            size_t o = ((size_t)z * 32 + blockIdx.x) * NPIX + m0 + row;
            stM[o] = mx; stS[o] = s;
        }
    }
}

// ---------------------------------------------------------------------------
__global__ void __launch_bounds__(256)
combine_stats(const float* __restrict__ stM, const float* __restrict__ stS,
              float* __restrict__ rowM, float* __restrict__ rowIL)
{
    const int idx = blockIdx.x * 256 + threadIdx.x;
    if (idx >= BATCH * NPIX) return;
    const int z = idx >> 12, i = idx & (NPIX - 1);
    float m = -3.0e38f;
#pragma unroll 4
    for (int t = 0; t < 32; ++t)
        m = fmaxf(m, stM[((size_t)z * 32 + t) * NPIX + i]);
    float l = 0.f;
#pragma unroll 4
    for (int t = 0; t < 32; ++t) {
        size_t o = ((size_t)z * 32 + t) * NPIX + i;
        l += stS[o] * __expf(stM[o] - m);
    }
    rowM[idx] = m;
    rowIL[idx] = 1.0f / l;
}

// ---------------------------------------------------------------------------
__global__ void __launch_bounds__(256)
tsplit_both(const float* __restrict__ Fc, const float* __restrict__ Fs,
            fp16* __restrict__ ohc, fp16* __restrict__ olc,
            fp16* __restrict__ ohs, fp16* __restrict__ ols)
{
    __shared__ float t[32][33];
    const int zz = blockIdx.z;
    const int b = zz & 3;
    const float* X = (zz < 4) ? Fc : Fs;
    fp16* oh = (zz < 4) ? ohc : ohs;
    fp16* ol = (zz < 4) ? olc : ols;
    const int pb = blockIdx.x * 32, cb = blockIdx.y * 32;
    const float* src = X + (size_t)b * CDIM * NPIX;
#pragma unroll
    for (int j = 0; j < 4; ++j) {
        int c = cb + threadIdx.y + j * 8;
        t[threadIdx.y + j * 8][threadIdx.x] = src[(size_t)c * NPIX + pb + threadIdx.x];
    }
    __syncthreads();
#pragma unroll
    for (int j = 0; j < 4; ++j) {
        int p = pb + threadIdx.y + j * 8;
        float v = t[threadIdx.x][threadIdx.y + j * 8];
        size_t o = (size_t)b * NPIX * CDIM + (size_t)p * CDIM + cb + threadIdx.x;
        fp16 h, l; split2h(v, h, l);
        oh[o] = h; ol[o] = l;
    }
}

__global__ void __launch_bounds__(256)
wsplit_all(const float* __restrict__ w0, const float* __restrict__ w1,
           const float* __restrict__ w2, const float* __restrict__ w3,
           fp16* __restrict__ h0, fp16* __restrict__ l0,
           fp16* __restrict__ h1, fp16* __restrict__ l1,
           fp16* __restrict__ h2, fp16* __restrict__ l2,
           fp16* __restrict__ h3, fp16* __restrict__ l3)
{
    const float* w = (blockIdx.y == 0) ? w0 : (blockIdx.y == 1) ? w1 : (blockIdx.y == 2) ? w2 : w3;
    fp16* hh = (blockIdx.y == 0) ? h0 : (blockIdx.y == 1) ? h1 : (blockIdx.y == 2) ? h2 : h3;
    fp16* ll = (blockIdx.y == 0) ? l0 : (blockIdx.y == 1) ? l1 : (blockIdx.y == 2) ? l2 : l3;
    int i = blockIdx.x * 256 + threadIdx.x;
    if (i < CDIM * CDIM) { fp16 a, b; split2h(w[i], a, b); hh[i] = a; ll[i] = b; }
}

// ---------------------------------------------------------------------------
extern "C" void kernel_launch(void* const* d_in, const int* in_sizes, int n_in,
                              void* d_out, int out_size)
{
    const float* F_c = (const float*)d_in[0];
    const float* F_s = (const float*)d_in[1];
    const float* w_f = (const float*)d_in[2];
    const float* b_f = (const float*)d_in[3];
    const float* w_g = (const float*)d_in[4];
    const float* b_g = (const float*)d_in[5];
    const float* w_h = (const float*)d_in[6];
    const float* b_h = (const float*)d_in[7];
    const float* w_o = (const float*)d_in[8];
    const float* b_o = (const float*)d_in[9];
    float* out = (float*)d_out;

    fp16 *FcTh, *FcTl, *FsTh, *FsTl, *wfh, *wfl, *wgh, *wgl, *whh, *whl, *woh, *wol;
    fp16 *Fqh, *Fql, *Gh, *Gl, *Hvh, *Rh, *E;
    float *stM, *stS, *rowM, *rowIL;
    cudaGetSymbolAddress((void**)&FcTh, g_FcT_h); cudaGetSymbolAddress((void**)&FcTl, g_FcT_l);
    cudaGetSymbolAddress((void**)&FsTh, g_FsT_h); cudaGetSymbolAddress((void**)&FsTl, g_FsT_l);
    cudaGetSymbolAddress((void**)&wfh, g_wf_h);   cudaGetSymbolAddress((void**)&wfl, g_wf_l);
    cudaGetSymbolAddress((void**)&wgh, g_wg_h);   cudaGetSymbolAddress((void**)&wgl, g_wg_l);
    cudaGetSymbolAddress((void**)&whh, g_wh_h);   cudaGetSymbolAddress((void**)&whl, g_wh_l);
    cudaGetSymbolAddress((void**)&woh, g_wo_h);   cudaGetSymbolAddress((void**)&wol, g_wo_l);
    cudaGetSymbolAddress((void**)&Fqh, g_Fq_h);   cudaGetSymbolAddress((void**)&Fql, g_Fq_l);
    cudaGetSymbolAddress((void**)&Gh,  g_G_h);    cudaGetSymbolAddress((void**)&Gl,  g_G_l);
    cudaGetSymbolAddress((void**)&Hvh, g_Hv_h);   cudaGetSymbolAddress((void**)&Rh,  g_R_h);
    cudaGetSymbolAddress((void**)&E,   g_E);
    cudaGetSymbolAddress((void**)&stM, g_stM);    cudaGetSymbolAddress((void**)&stS, g_stS);
    cudaGetSymbolAddress((void**)&rowM, g_rowM);  cudaGetSymbolAddress((void**)&rowIL, g_rowIL);

    cudaFuncSetAttribute((const void*)conv_merged, cudaFuncAttributeMaxDynamicSharedMemorySize, DSMEM);
    cudaFuncSetAttribute((const void*)mma_gemm<3,false,3>, cudaFuncAttributeMaxDynamicSharedMemorySize, DSMEM);
    cudaFuncSetAttribute((const void*)mma_gemm<2,true ,1>, cudaFuncAttributeMaxDynamicSharedMemorySize, DSMEM_F);
    cudaFuncSetAttribute((const void*)mma_gemm<0,false,2>, cudaFuncAttributeMaxDynamicSharedMemorySize, DSMEM);

    const long long cn = (long long)NPIX * CDIM;
    const long long nn = (long long)NPIX * NPIX;

    dim3 gConv(NPIX / 128, CDIM / 128, BATCH);     // 32 x 2 x 4
    dim3 gConvM(NPIX / 128, CDIM / 128, 3 * BATCH);// 32 x 2 x 12
    dim3 gS(NPIX / 128, NPIX / 128, BATCH);        // 32 x 32 x 4

    // L1, L2: conversions
    wsplit_all<<<dim3(256, 4), 256>>>(w_f, w_g, w_h, w_o,
        wfh, wfl, wgh, wgl, whh, whl, woh, wol);
    tsplit_both<<<dim3(128, 8, 8), dim3(32, 8)>>>(F_c, F_s, FcTh, FcTl, FsTh, FsTl);
    // L3: merged G1+G2+G3 (Hv 2-pass)
    conv_merged<<<gConvM, 256, DSMEM>>>(wfh, wfl, wgh, wgl, whh, whl,
        FcTh, FcTl, FsTh, FsTl, b_f, b_g, b_h, Fqh, Fql, Gh, Gl, Hvh);
    // L4 (G4): E + stats (3-pass)
    mma_gemm<3,false,3><<<gS, 256, DSMEM>>>(Fqh, Fql, Gh, Gl,
        CDIM, CDIM, CDIM, NPIX, cn, cn, nn, nullptr, nullptr, E, nullptr,
        nullptr, nullptr, nullptr, nullptr, stM, stS);
    // L5: stats fold
    combine_stats<<<(BATCH * NPIX + 255) / 256, 256>>>(stM, stS, rowM, rowIL);
    // L6 (G5): R_t hi only (1-pass, FUSEB)
    mma_gemm<2,true,1><<<gConv, 256, DSMEM_F>>>(Hvh, nullptr, nullptr, nullptr,
        NPIX, NPIX, NPIX, CDIM, cn, nn, cn, nullptr, nullptr, Rh, nullptr,
        E, rowM, rowIL, stM, nullptr, nullptr);
    // L7 (G6): out = w_o @ R + b_o (2-pass)
    mma_gemm<0,false,2><<<gConv, 256, DSMEM>>>(woh, wol, Rh, nullptr,
        CDIM, CDIM, CDIM, NPIX, 0, cn, cn, b_o, out, nullptr, nullptr,
        nullptr, nullptr, nullptr, nullptr, nullptr, nullptr);
}

// round 15
// speedup vs baseline: 1.0643x; 1.0162x over previous
#include <cuda_runtime.h>
#include <cuda_fp16.h>
#include <cstdint>

#define BATCH 4
#define CDIM  256
#define NPIX  4096
typedef __half fp16;

#define CN ((size_t)BATCH * NPIX * CDIM)      // 4,194,304
#define NN ((size_t)BATCH * NPIX * NPIX)      // 67,108,864

// ---------------------------------------------------------------------------
// Device scratch
// ---------------------------------------------------------------------------
__device__ fp16  g_FcT_h[CN], g_FcT_l[CN];    // F_c transposed [b][p][c]
__device__ fp16  g_FsT_h[CN], g_FsT_l[CN];
__device__ fp16  g_wf_h[CDIM*CDIM], g_wf_l[CDIM*CDIM];
__device__ fp16  g_wg_h[CDIM*CDIM], g_wg_l[CDIM*CDIM];
__device__ fp16  g_wh_h[CDIM*CDIM], g_wh_l[CDIM*CDIM];
__device__ fp16  g_wo_h[CDIM*CDIM], g_wo_l[CDIM*CDIM];
__device__ fp16  g_Fq_h[CN], g_Fq_l[CN];      // [b][i][c]
__device__ fp16  g_G_h [CN], g_G_l [CN];      // [b][j][c]
__device__ fp16  g_Hv_h[CN];                  // [b][c][j]
__device__ fp16  g_R_h [CN];                  // [b][i][c]
__device__ fp16  g_E[NN];                     // E = exp(S - m_tile), fp16
__device__ float g_stM[(size_t)BATCH * 32 * NPIX];
__device__ float g_stS[(size_t)BATCH * 32 * NPIX];

// ---------------------------------------------------------------------------
// PTX helpers (sm_80-level only)
// ---------------------------------------------------------------------------
__device__ __forceinline__ uint32_t smem_u32(const void* p) {
    uint32_t a;
    asm("{ .reg .u64 t; cvta.to.shared.u64 t, %1; cvt.u32.u64 %0, t; }" : "=r"(a) : "l"(p));
    return a;
}
#define CPA(s, g) asm volatile("cp.async.cg.shared.global [%0], [%1], 16;" :: "r"(s), "l"(g) : "memory")
#define CPC()     asm volatile("cp.async.commit_group;" ::: "memory")
#define CPW(n)    asm volatile("cp.async.wait_group %0;" :: "n"(n) : "memory")

__device__ __forceinline__ void ldsm4(uint32_t* r, uint32_t a) {
    asm volatile("ldmatrix.sync.aligned.m8n8.x4.shared.b16 {%0,%1,%2,%3}, [%4];"
        : "=r"(r[0]), "=r"(r[1]), "=r"(r[2]), "=r"(r[3]) : "r"(a));
}
__device__ __forceinline__ void ldsm2(uint32_t* r, uint32_t a) {
    asm volatile("ldmatrix.sync.aligned.m8n8.x2.shared.b16 {%0,%1}, [%2];"
        : "=r"(r[0]), "=r"(r[1]) : "r"(a));
}
__device__ __forceinline__ void mma_fp16(float* c, const uint32_t* a, const uint32_t* b) {
    asm volatile("mma.sync.aligned.m16n8k16.row.col.f32.f16.f16.f32 "
        "{%0,%1,%2,%3}, {%4,%5,%6,%7}, {%8,%9}, {%0,%1,%2,%3};"
        : "+f"(c[0]), "+f"(c[1]), "+f"(c[2]), "+f"(c[3])
        : "r"(a[0]), "r"(a[1]), "r"(a[2]), "r"(a[3]), "r"(b[0]), "r"(b[1]));
}
__device__ __forceinline__ void split2h(float x, fp16& h, fp16& l) {
    h = __float2half_rn(x);
    l = __float2half_rn(x - __half2float(h));
}

#define RSB      80
#define TILE_SB  (128 * RSB)     // 10240
#define STAGE_SB (4 * TILE_SB)   // 40960
#define SF_SB    (128 * 80)      // fp16 E staging
#define DSMEM    (2 * STAGE_SB)                 // 81920
#define DSMEM_F  (2 * STAGE_SB + SF_SB + 1024)  // 93184 (E staging + stats)

// ===========================================================================
// Merged conv GEMM: grid (32, 2, 12).
// z<4 -> Fq (3-pass, EPI2); z<8 -> G (3-pass, EPI2); z>=8 -> Hv (2-pass, EPI1)
// ===========================================================================
__global__ void __launch_bounds__(256, 2)
conv_merged(const fp16* __restrict__ wfh, const fp16* __restrict__ wfl,
            const fp16* __restrict__ wgh, const fp16* __restrict__ wgl,
            const fp16* __restrict__ whh, const fp16* __restrict__ whl,
            const fp16* __restrict__ FcTh, const fp16* __restrict__ FcTl,
            const fp16* __restrict__ FsTh, const fp16* __restrict__ FsTl,
            const float* __restrict__ b_f, const float* __restrict__ b_g,
            const float* __restrict__ b_h,
            fp16* __restrict__ Fqh, fp16* __restrict__ Fql,
            fp16* __restrict__ Gh,  fp16* __restrict__ Gl,
            fp16* __restrict__ Hvh)
{
    extern __shared__ char smem[];
    const uint32_t sb = smem_u32(smem);
    const int tid = threadIdx.x;
    const int lane = tid & 31, wid = tid >> 5;
    const int wm = wid >> 2, wn = wid & 3;
    const int m0 = blockIdx.y * 128, n0 = blockIdx.x * 128;

    const int zz = blockIdx.z, grp = zz >> 2, b = zz & 3;
    const size_t cn = (size_t)NPIX * CDIM;
    const fp16 *Ah, *Al, *Bh, *Bl;
    const float* bias;
    fp16 *oH, *oL;
    if (grp == 0) {
        Ah = wfh; Al = wfl; Bh = FcTh + b * cn; Bl = FcTl + b * cn;
        bias = b_f; oH = Fqh + b * cn; oL = Fql + b * cn;
    } else if (grp == 1) {
        Ah = wgh; Al = wgl; Bh = FsTh + b * cn; Bl = FsTl + b * cn;
        bias = b_g; oH = Gh + b * cn; oL = Gl + b * cn;
    } else {
        Ah = whh; Al = whl; Bh = FsTh + b * cn; Bl = FsTl + b * cn;
        bias = b_h; oH = Hvh + b * cn; oL = nullptr;
    }
    const bool doP3 = (grp < 2);
    const int epi = (grp < 2) ? 2 : 1;
    const int ldo = (epi == 2) ? CDIM : NPIX;

    const int nk = CDIM / 32;   // 8
    const int r0 = tid >> 2, c0 = tid & 3, r1 = r0 + 64;

    auto issue = [&](int kc) {
        if (kc >= nk) return;
        const uint32_t s0 = sb + (uint32_t)(kc & 1) * STAGE_SB;
        const fp16* srcs[4] = {Ah, Al, Bh, Bl};
#pragma unroll
        for (int t = 0; t < 4; ++t) {
            if (t == 3 && !doP3) continue;
            const fp16* g0 = srcs[t] + (size_t)(r0 + ((t < 2) ? m0 : n0)) * CDIM + kc * 32 + c0 * 8;
            const fp16* g1 = srcs[t] + (size_t)(r1 + ((t < 2) ? m0 : n0)) * CDIM + kc * 32 + c0 * 8;
            CPA(s0 + t * TILE_SB + r0 * RSB + c0 * 16, g0);
            CPA(s0 + t * TILE_SB + r1 * RSB + c0 * 16, g1);
        }
    };

    float acc[4][4][4];
#pragma unroll
    for (int i = 0; i < 4; ++i)
#pragma unroll
        for (int j = 0; j < 4; ++j)
#pragma unroll
            for (int q = 0; q < 4; ++q) acc[i][j][q] = 0.f;

    issue(0); CPC();
    issue(1); CPC();

    const int aRow = lane & 15;
    const int aKB  = (lane >> 4) * 16;
    const int bRow = lane & 7;
    const int bKB  = ((lane >> 3) & 1) * 16;

    for (int kc = 0; kc < nk; ++kc) {
        CPW(1);
        __syncthreads();
        const uint32_t s0 = sb + (uint32_t)(kc & 1) * STAGE_SB;
        const uint32_t aH = s0, aL = s0 + TILE_SB;
        const uint32_t bH = s0 + 2 * TILE_SB, bL = s0 + 3 * TILE_SB;
#pragma unroll
        for (int ks = 0; ks < 2; ++ks) {
            uint32_t Af[2][4][4];
#pragma unroll
            for (int i = 0; i < 4; ++i) {
                const uint32_t off = (uint32_t)(wm * 64 + i * 16 + aRow) * RSB + ks * 32 + aKB;
                ldsm4(Af[0][i], aH + off);
                ldsm4(Af[1][i], aL + off);
            }
#pragma unroll
            for (int jp = 0; jp < 2; ++jp) {
                uint32_t Bf[2][2][2];
#pragma unroll
                for (int jj = 0; jj < 2; ++jj) {
                    const int j = jp * 2 + jj;
                    const uint32_t off = (uint32_t)(wn * 32 + j * 8 + bRow) * RSB + ks * 32 + bKB;
                    ldsm2(Bf[0][jj], bH + off);
                    if (doP3) ldsm2(Bf[1][jj], bL + off);
                }
#pragma unroll
                for (int jj = 0; jj < 2; ++jj)
#pragma unroll
                    for (int i = 0; i < 4; ++i)
                        mma_fp16(acc[i][jp * 2 + jj], Af[0][i], Bf[0][jj]);
#pragma unroll
                for (int jj = 0; jj < 2; ++jj)
#pragma unroll
                    for (int i = 0; i < 4; ++i)
                        mma_fp16(acc[i][jp * 2 + jj], Af[1][i], Bf[0][jj]);
                if (doP3)
#pragma unroll
                    for (int jj = 0; jj < 2; ++jj)
#pragma unroll
                        for (int i = 0; i < 4; ++i)
                            mma_fp16(acc[i][jp * 2 + jj], Af[0][i], Bf[1][jj]);
            }
        }
        __syncthreads();
        issue(kc + 2); CPC();
    }

    // ---- epilogue: stage D (+bias on m) ----
    float* stg = (float*)smem;
    const int gid = lane >> 2, tig = lane & 3;
#pragma unroll
    for (int i = 0; i < 4; ++i) {
        const int ml = wm * 64 + i * 16 + gid;
        const float bv0 = bias[m0 + ml];
        const float bv8 = bias[m0 + ml + 8];
#pragma unroll
        for (int j = 0; j < 4; ++j) {
            const int nl = wn * 32 + j * 8 + tig * 2;
            stg[ml * 132 + nl]           = acc[i][j][0] + bv0;
            stg[ml * 132 + nl + 1]       = acc[i][j][1] + bv0;
            stg[(ml + 8) * 132 + nl]     = acc[i][j][2] + bv8;
            stg[(ml + 8) * 132 + nl + 1] = acc[i][j][3] + bv8;
        }
    }
    __syncthreads();

    const int row = tid >> 1, half = tid & 1;
    if (epi == 2) {
        const int n = row, mh = half * 64;
        const size_t base = (size_t)(n0 + n) * ldo + m0 + mh;
#pragma unroll
        for (int v = 0; v < 8; ++v) {
            uint32_t hw[4], lw[4];
#pragma unroll
            for (int q = 0; q < 4; ++q) {
                float x0 = stg[(mh + v * 8 + q * 2) * 132 + n];
                float x1 = stg[(mh + v * 8 + q * 2 + 1) * 132 + n];
                fp16 h0, l0, h1, l1;
                split2h(x0, h0, l0); split2h(x1, h1, l1);
                __half2 hp = __halves2half2(h0, h1), lp = __halves2half2(l0, l1);
                hw[q] = *(uint32_t*)&hp; lw[q] = *(uint32_t*)&lp;
            }
            *(uint4*)(oH + base + v * 8) = make_uint4(hw[0], hw[1], hw[2], hw[3]);
            *(uint4*)(oL + base + v * 8) = make_uint4(lw[0], lw[1], lw[2], lw[3]);
        }
    } else {
        const size_t base = (size_t)(m0 + row) * ldo + n0 + half * 64;
#pragma unroll
        for (int v = 0; v < 8; ++v) {
            uint32_t hw[4];
#pragma unroll
            for (int q = 0; q < 4; ++q) {
                float x0 = stg[row * 132 + half * 64 + v * 8 + q * 2];
                float x1 = stg[row * 132 + half * 64 + v * 8 + q * 2 + 1];
                __half2 hp = __floats2half2_rn(x0, x1);
                hw[q] = *(uint32_t*)&hp;
            }
            *(uint4*)(oH + base + v * 8) = make_uint4(hw[0], hw[1], hw[2], hw[3]);
        }
    }
}

// ===========================================================================
// Generic GEMM. EPI: 0 fp32(+bias); 2 fp16 transposed; 3 E + stats.
// FUSEB: B from E * exp(mt-m)*il; row stats computed in-kernel from stM/stS.
// ===========================================================================
template <int EPI, bool FUSEB, int PASSES>
__global__ void __launch_bounds__(256, 2)
mma_gemm(const fp16* __restrict__ Ah_, const fp16* __restrict__ Al_,
         const fp16* __restrict__ Bh_, const fp16* __restrict__ Bl_,
         int K, int lda, int ldb, int ldo,
         long long sA, long long sB, long long sO,
         const float* __restrict__ bias,
         float* __restrict__ outF, fp16* __restrict__ oH, fp16* __restrict__ oL,
         const fp16* __restrict__ Efp,
         const float* __restrict__ stMg, const float* __restrict__ stSg,
         float* __restrict__ stM, float* __restrict__ stS)
{
    extern __shared__ char smem[];
    const uint32_t sb = smem_u32(smem);
    const int tid = threadIdx.x;
    const int lane = tid & 31, wid = tid >> 5;
    const int wm = wid >> 2, wn = wid & 3;
    const int z = blockIdx.z;
    const int m0 = blockIdx.y * 128, n0 = blockIdx.x * 128;

    const fp16* pT[4] = {Ah_ + (size_t)z * sA,
                         (PASSES >= 2) ? Al_ + (size_t)z * sA : nullptr,
                         FUSEB ? nullptr : Bh_ + (size_t)z * sB,
                         (!FUSEB && PASSES >= 3) ? Bl_ + (size_t)z * sB : nullptr};
    const int nk = K / 32;
    const int r0 = tid >> 2, c0 = tid & 3, r1 = r0 + 64;

    auto issueA = [&](int kc) {
        if (kc >= nk) return;
        const uint32_t s0 = sb + (uint32_t)(kc & 1) * STAGE_SB;
#pragma unroll
        for (int t = 0; t < 4; ++t) {
            if (t == 1 && PASSES < 2) continue;
            if (t >= 2 && FUSEB) continue;
            if (t == 3 && PASSES < 3) continue;
            const int ld = (t < 2) ? lda : ldb;
            const int base = (t < 2) ? m0 : n0;
            const fp16* g0 = pT[t] + (size_t)(base + r0) * ld + kc * 32 + c0 * 8;
            const fp16* g1 = pT[t] + (size_t)(base + r1) * ld + kc * 32 + c0 * 8;
            CPA(s0 + t * TILE_SB + r0 * RSB + c0 * 16, g0);
            CPA(s0 + t * TILE_SB + r1 * RSB + c0 * 16, g1);
        }
    };

    const int pr = tid >> 1, jh = tid & 1;
    const uint32_t sf = sb + 2 * STAGE_SB;
    float mrow = 0.f, il = 0.f;
    const fp16* Erow = nullptr;
    float* mS  = (float*)(smem + 2 * STAGE_SB + SF_SB);
    float* ilS = mS + 128;
    if (FUSEB)
        Erow = Efp + (size_t)z * sB + (size_t)(n0 + pr) * ldb;

    auto issueS = [&](int kc) {
        if (kc >= nk) return;
        const uint32_t d = sf + pr * 80 + jh * 32;
        const fp16* g = Erow + kc * 32 + jh * 16;
        CPA(d, g); CPA(d + 16, g + 8);
    };
    auto convB = [&](int kc) {
        const uint32_t s0 = sb + (kc & 1) * STAGE_SB;
        const int tile = kc >> 2;
        const float st = stMg[((size_t)z * 32 + tile) * NPIX + (n0 + pr)];
        const float scale = __expf(st - mrow) * il;
        const __half2* Ef = (const __half2*)(smem + 2 * STAGE_SB + pr * 80 + jh * 32);
        const uint32_t dH = s0 + 2 * TILE_SB + pr * RSB + jh * 32;
        uint32_t w[8];
#pragma unroll
        for (int q = 0; q < 8; ++q) {
            float2 e = __half22float2(Ef[q]);
            __half2 hp = __floats2half2_rn(e.x * scale, e.y * scale);
            w[q] = *(uint32_t*)&hp;
        }
        asm volatile("st.shared.v4.b32 [%0], {%1,%2,%3,%4};"
            :: "r"(dH), "r"(w[0]), "r"(w[1]), "r"(w[2]), "r"(w[3]) : "memory");
        asm volatile("st.shared.v4.b32 [%0], {%1,%2,%3,%4};"
            :: "r"(dH + 16), "r"(w[4]), "r"(w[5]), "r"(w[6]), "r"(w[7]) : "memory");
    };

    float acc[4][4][4];
#pragma unroll
    for (int i = 0; i < 4; ++i)
#pragma unroll
        for (int j = 0; j < 4; ++j)
#pragma unroll
            for (int q = 0; q < 4; ++q) acc[i][j][q] = 0.f;

    issueA(0); if (FUSEB) issueS(0); CPC();
    issueA(1); CPC();

    if (FUSEB) {
        // per-CTA row stats (overlaps the in-flight cp.async groups)
        if (tid < 128) {
            const int irow = n0 + tid;
            float m = -3.0e38f;
#pragma unroll 4
            for (int t = 0; t < 32; ++t)
                m = fmaxf(m, stMg[((size_t)z * 32 + t) * NPIX + irow]);
            float l = 0.f;
#pragma unroll 4
            for (int t = 0; t < 32; ++t) {
                size_t o = ((size_t)z * 32 + t) * NPIX + irow;
                l += stSg[o] * __expf(stMg[o] - m);
            }
            mS[tid] = m; ilS[tid] = 1.0f / l;
        }
        __syncthreads();
        mrow = mS[pr];
        il   = ilS[pr];
    }

    const int aRow = lane & 15;
    const int aKB  = (lane >> 4) * 16;
    const int bRow = lane & 7;
    const int bKB  = ((lane >> 3) & 1) * 16;

    for (int kc = 0; kc < nk; ++kc) {
        CPW(1);
        if (FUSEB) convB(kc);
        __syncthreads();
        const uint32_t s0 = sb + (uint32_t)(kc & 1) * STAGE_SB;
        const uint32_t aH = s0, aL = s0 + TILE_SB;
        const uint32_t bH = s0 + 2 * TILE_SB, bL = s0 + 3 * TILE_SB;
#pragma unroll
        for (int ks = 0; ks < 2; ++ks) {
            uint32_t Af[2][4][4];
#pragma unroll
            for (int i = 0; i < 4; ++i) {
                const uint32_t off = (uint32_t)(wm * 64 + i * 16 + aRow) * RSB + ks * 32 + aKB;
                ldsm4(Af[0][i], aH + off);
                if (PASSES >= 2) ldsm4(Af[1][i], aL + off);
            }
#pragma unroll
            for (int jp = 0; jp < 2; ++jp) {
                uint32_t Bf[2][2][2];
#pragma unroll
                for (int jj = 0; jj < 2; ++jj) {
                    const int j = jp * 2 + jj;
                    const uint32_t off = (uint32_t)(wn * 32 + j * 8 + bRow) * RSB + ks * 32 + bKB;
                    ldsm2(Bf[0][jj], bH + off);
                    if (PASSES >= 3) ldsm2(Bf[1][jj], bL + off);
                }
#pragma unroll
                for (int jj = 0; jj < 2; ++jj)
#pragma unroll
                    for (int i = 0; i < 4; ++i)
                        mma_fp16(acc[i][jp * 2 + jj], Af[0][i], Bf[0][jj]);
                if (PASSES >= 2)
#pragma unroll
                    for (int jj = 0; jj < 2; ++jj)
#pragma unroll
                        for (int i = 0; i < 4; ++i)
                            mma_fp16(acc[i][jp * 2 + jj], Af[1][i], Bf[0][jj]);
                if (PASSES >= 3)
#pragma unroll
                    for (int jj = 0; jj < 2; ++jj)
#pragma unroll
                        for (int i = 0; i < 4; ++i)
                            mma_fp16(acc[i][jp * 2 + jj], Af[0][i], Bf[1][jj]);
            }
        }
        __syncthreads();
        if (FUSEB) { issueS(kc + 1); CPC(); issueA(kc + 2); CPC(); }
        else       { issueA(kc + 2); CPC(); }
    }

    // ---- epilogue ----
    float* stg = (float*)smem;
    const int gid = lane >> 2, tig = lane & 3;
#pragma unroll
    for (int i = 0; i < 4; ++i) {
        const int ml = wm * 64 + i * 16 + gid;
        const float bv0 = bias ? bias[m0 + ml] : 0.f;
        const float bv8 = bias ? bias[m0 + ml + 8] : 0.f;
#pragma unroll
        for (int j = 0; j < 4; ++j) {
            const int nl = wn * 32 + j * 8 + tig * 2;
            stg[ml * 132 + nl]           = acc[i][j][0] + bv0;
            stg[ml * 132 + nl + 1]       = acc[i][j][1] + bv0;
            stg[(ml + 8) * 132 + nl]     = acc[i][j][2] + bv8;
            stg[(ml + 8) * 132 + nl + 1] = acc[i][j][3] + bv8;
        }
    }
    __syncthreads();

    const int row = tid >> 1, half = tid & 1;
    if (EPI == 0) {
        float* dst = outF + (size_t)z * sO + (size_t)(m0 + row) * ldo + n0 + half * 64;
        const float4* s4 = (const float4*)&stg[row * 132 + half * 64];
#pragma unroll
        for (int i = 0; i < 16; ++i) ((float4*)dst)[i] = s4[i];
    } else if (EPI == 2) {
        const int n = row, mh = half * 64;
        const size_t base = (size_t)z * sO + (size_t)(n0 + n) * ldo + m0 + mh;
#pragma unroll
        for (int v = 0; v < 8; ++v) {
            uint32_t hw[4];
#pragma unroll
            for (int q = 0; q < 4; ++q) {
                float x0 = stg[(mh + v * 8 + q * 2) * 132 + n];
                float x1 = stg[(mh + v * 8 + q * 2 + 1) * 132 + n];
                __half2 hp = __floats2half2_rn(x0, x1);
                hw[q] = *(uint32_t*)&hp;
            }
            *(uint4*)(oH + base + v * 8) = make_uint4(hw[0], hw[1], hw[2], hw[3]);
        }
    } else {   // EPI == 3
        const size_t base = (size_t)z * sO + (size_t)(m0 + row) * ldo + n0 + half * 64;
        const float* src = &stg[row * 132 + half * 64];
        float mx = -3.0e38f;
#pragma unroll
        for (int q = 0; q < 64; ++q) mx = fmaxf(mx, src[q]);
        mx = fmaxf(mx, __shfl_xor_sync(0xffffffffu, mx, 1));
        float s = 0.f;
#pragma unroll
        for (int v = 0; v < 8; ++v) {
            uint32_t w[4];
#pragma unroll
            for (int q = 0; q < 4; ++q) {
                float e0 = __expf(src[v * 8 + q * 2]     - mx);
                float e1 = __expf(src[v * 8 + q * 2 + 1] - mx);
                s += e0 + e1;
                __half2 hp = __floats2half2_rn(e0, e1);
                w[q] = *(uint32_t*)&hp;
            }
            *(uint4*)(oH + base + v * 8) = make_uint4(w[0], w[1], w[2], w[3]);
        }
        s += __shfl_xor_sync(0xffffffffu, s, 1);
        if (half == 0) {
            size_t o = ((size_t)z * 32 + blockIdx.x) * NPIX + m0 + row;
            stM[o] = mx; stS[o] = s;
        }
    }
}

// ---------------------------------------------------------------------------
// fp32 [b][c][p] -> fp16 hi/lo transposed [b][p][c].
// Tile 64c x 32p; writes are __half2 with 32 lanes covering 128B rows.
// grid (NPIX/32, CDIM/64, 8), block 256.
// ---------------------------------------------------------------------------
__global__ void __launch_bounds__(256)
tsplit_both(const float* __restrict__ Fc, const float* __restrict__ Fs,
            fp16* __restrict__ ohc, fp16* __restrict__ olc,
            fp16* __restrict__ ohs, fp16* __restrict__ ols)
{
    __shared__ float t[32][65];   // [p][c]
    const int zz = blockIdx.z;
    const int b = zz & 3;
    const float* X = (zz < 4) ? Fc : Fs;
    fp16* oh = (zz < 4) ? ohc : ohs;
    fp16* ol = (zz < 4) ? olc : ols;
    const int pb = blockIdx.x * 32, cb = blockIdx.y * 64;
    const float* src = X + (size_t)b * CDIM * NPIX;
    const int tid = threadIdx.x;

    // load: 64 c-rows x 32 p, coalesced over p (128B per c-row)
    const int lp = tid & 31, lc = tid >> 5;   // 8 c per iteration
#pragma unroll
    for (int it = 0; it < 8; ++it) {
        const int c = lc + it * 8;
        t[lp][c] = src[(size_t)(cb + c) * NPIX + pb + lp];
    }
    __syncthreads();

    // write: thread covers one c-pair; 32 lanes = 64 c = 128B contiguous
    const int wpair = tid & 31, wp = tid >> 5;  // 8 p per iteration
#pragma unroll
    for (int it = 0; it < 4; ++it) {
        const int p = wp + it * 8;
        const float x0 = t[p][wpair * 2];
        const float x1 = t[p][wpair * 2 + 1];
        fp16 h0, l0, h1, l1;
        split2h(x0, h0, l0); split2h(x1, h1, l1);
        __half2 hp = __halves2half2(h0, h1), lpk = __halves2half2(l0, l1);
        const size_t o = (size_t)b * NPIX * CDIM + (size_t)(pb + p) * CDIM + cb + wpair * 2;
        *(__half2*)(oh + o) = hp;
        *(__half2*)(ol + o) = lpk;
    }
}

__global__ void __launch_bounds__(256)
wsplit_all(const float* __restrict__ w0, const float* __restrict__ w1,
           const float* __restrict__ w2, const float* __restrict__ w3,
           fp16* __restrict__ h0, fp16* __restrict__ l0,
           fp16* __restrict__ h1, fp16* __restrict__ l1,
           fp16* __restrict__ h2, fp16* __restrict__ l2,
           fp16* __restrict__ h3, fp16* __restrict__ l3)
{
    const float* w = (blockIdx.y == 0) ? w0 : (blockIdx.y == 1) ? w1 : (blockIdx.y == 2) ? w2 : w3;
    fp16* hh = (blockIdx.y == 0) ? h0 : (blockIdx.y == 1) ? h1 : (blockIdx.y == 2) ? h2 : h3;
    fp16* ll = (blockIdx.y == 0) ? l0 : (blockIdx.y == 1) ? l1 : (blockIdx.y == 2) ? l2 : l3;
    int i = (blockIdx.x * 256 + threadIdx.x) * 2;
    if (i < CDIM * CDIM) {
        float2 v = *(const float2*)(w + i);
        fp16 a0, b0, a1, b1;
        split2h(v.x, a0, b0); split2h(v.y, a1, b1);
        *(__half2*)(hh + i) = __halves2half2(a0, a1);
        *(__half2*)(ll + i) = __halves2half2(b0, b1);
    }
}

// ---------------------------------------------------------------------------
extern "C" void kernel_launch(void* const* d_in, const int* in_sizes, int n_in,
                              void* d_out, int out_size)
{
    const float* F_c = (const float*)d_in[0];
    const float* F_s = (const float*)d_in[1];
    const float* w_f = (const float*)d_in[2];
    const float* b_f = (const float*)d_in[3];
    const float* w_g = (const float*)d_in[4];
    const float* b_g = (const float*)d_in[5];
    const float* w_h = (const float*)d_in[6];
    const float* b_h = (const float*)d_in[7];
    const float* w_o = (const float*)d_in[8];
    const float* b_o = (const float*)d_in[9];
    float* out = (float*)d_out;

    fp16 *FcTh, *FcTl, *FsTh, *FsTl, *wfh, *wfl, *wgh, *wgl, *whh, *whl, *woh, *wol;
    fp16 *Fqh, *Fql, *Gh, *Gl, *Hvh, *Rh, *E;
    float *stM, *stS;
    cudaGetSymbolAddress((void**)&FcTh, g_FcT_h); cudaGetSymbolAddress((void**)&FcTl, g_FcT_l);
    cudaGetSymbolAddress((void**)&FsTh, g_FsT_h); cudaGetSymbolAddress((void**)&FsTl, g_FsT_l);
    cudaGetSymbolAddress((void**)&wfh, g_wf_h);   cudaGetSymbolAddress((void**)&wfl, g_wf_l);
    cudaGetSymbolAddress((void**)&wgh, g_wg_h);   cudaGetSymbolAddress((void**)&wgl, g_wg_l);
    cudaGetSymbolAddress((void**)&whh, g_wh_h);   cudaGetSymbolAddress((void**)&whl, g_wh_l);
    cudaGetSymbolAddress((void**)&woh, g_wo_h);   cudaGetSymbolAddress((void**)&wol, g_wo_l);
    cudaGetSymbolAddress((void**)&Fqh, g_Fq_h);   cudaGetSymbolAddress((void**)&Fql, g_Fq_l);
    cudaGetSymbolAddress((void**)&Gh,  g_G_h);    cudaGetSymbolAddress((void**)&Gl,  g_G_l);
    cudaGetSymbolAddress((void**)&Hvh, g_Hv_h);   cudaGetSymbolAddress((void**)&Rh,  g_R_h);
    cudaGetSymbolAddress((void**)&E,   g_E);
    cudaGetSymbolAddress((void**)&stM, g_stM);    cudaGetSymbolAddress((void**)&stS, g_stS);

    cudaFuncSetAttribute((const void*)conv_merged, cudaFuncAttributeMaxDynamicSharedMemorySize, DSMEM);
    cudaFuncSetAttribute((const void*)mma_gemm<3,false,3>, cudaFuncAttributeMaxDynamicSharedMemorySize, DSMEM);
    cudaFuncSetAttribute((const void*)mma_gemm<2,true ,1>, cudaFuncAttributeMaxDynamicSharedMemorySize, DSMEM_F);
    cudaFuncSetAttribute((const void*)mma_gemm<0,false,2>, cudaFuncAttributeMaxDynamicSharedMemorySize, DSMEM);

    const long long cn = (long long)NPIX * CDIM;
    const long long nn = (long long)NPIX * NPIX;

    dim3 gConv(NPIX / 128, CDIM / 128, BATCH);     // 32 x 2 x 4
    dim3 gConvM(NPIX / 128, CDIM / 128, 3 * BATCH);// 32 x 2 x 12
    dim3 gS(NPIX / 128, NPIX / 128, BATCH);        // 32 x 32 x 4

    // L1, L2: conversions
    wsplit_all<<<dim3(128, 4), 256>>>(w_f, w_g, w_h, w_o,
        wfh, wfl, wgh, wgl, whh, whl, woh, wol);
    tsplit_both<<<dim3(NPIX / 32, CDIM / 64, 8), 256>>>(F_c, F_s, FcTh, FcTl, FsTh, FsTl);
    // L3: merged G1+G2+G3 (Hv 2-pass)
    conv_merged<<<gConvM, 256, DSMEM>>>(wfh, wfl, wgh, wgl, whh, whl,
        FcTh, FcTl, FsTh, FsTl, b_f, b_g, b_h, Fqh, Fql, Gh, Gl, Hvh);
    // L4 (G4): E + stats (3-pass)
    mma_gemm<3,false,3><<<gS, 256, DSMEM>>>(Fqh, Fql, Gh, Gl,
        CDIM, CDIM, CDIM, NPIX, cn, cn, nn, nullptr, nullptr, E, nullptr,
        nullptr, nullptr, nullptr, stM, stS);
    // L5 (G5): R_t hi only (1-pass, FUSEB; row stats computed in-kernel)
    mma_gemm<2,true,1><<<gConv, 256, DSMEM_F>>>(Hvh, nullptr, nullptr, nullptr,
        NPIX, NPIX, NPIX, CDIM, cn, nn, cn, nullptr, nullptr, Rh, nullptr,
        E, stM, stS, nullptr, nullptr);
    // L6 (G6): out = w_o @ R + b_o (2-pass)
    mma_gemm<0,false,2><<<gConv, 256, DSMEM>>>(woh, wol, Rh, nullptr,
        CDIM, CDIM, CDIM, NPIX, 0, cn, cn, b_o, out, nullptr, nullptr,
        nullptr, nullptr, nullptr, nullptr, nullptr);
}

// round 16
// speedup vs baseline: 1.0779x; 1.0128x over previous
#include <cuda_runtime.h>
#include <cuda_fp16.h>
#include <cstdint>

#define BATCH 4
#define CDIM  256
#define NPIX  4096
typedef __half fp16;

#define CN ((size_t)BATCH * NPIX * CDIM)      // 4,194,304
#define NN ((size_t)BATCH * NPIX * NPIX)      // 67,108,864

// ---------------------------------------------------------------------------
// Device scratch
// ---------------------------------------------------------------------------
__device__ fp16  g_FcT_h[CN], g_FcT_l[CN];    // F_c transposed [b][p][c]
__device__ fp16  g_FsT_h[CN], g_FsT_l[CN];
__device__ fp16  g_wf_h[CDIM*CDIM], g_wf_l[CDIM*CDIM];
__device__ fp16  g_wg_h[CDIM*CDIM], g_wg_l[CDIM*CDIM];
__device__ fp16  g_wh_h[CDIM*CDIM], g_wh_l[CDIM*CDIM];
__device__ fp16  g_wo_h[CDIM*CDIM], g_wo_l[CDIM*CDIM];
__device__ fp16  g_Fq_h[CN], g_Fq_l[CN];      // [b][i][c]
__device__ fp16  g_G_h [CN], g_G_l [CN];      // [b][j][c]
__device__ fp16  g_Hv_h[CN];                  // [b][c][j]
__device__ fp16  g_R_h [CN];                  // [b][i][c]
__device__ fp16  g_E[NN];                     // E = exp(S - m_tile), fp16
__device__ float g_stM[(size_t)BATCH * 32 * NPIX];
__device__ float g_stS[(size_t)BATCH * 32 * NPIX];

// ---------------------------------------------------------------------------
// PTX helpers (sm_80-level only)
// ---------------------------------------------------------------------------
__device__ __forceinline__ uint32_t smem_u32(const void* p) {
    uint32_t a;
    asm("{ .reg .u64 t; cvta.to.shared.u64 t, %1; cvt.u32.u64 %0, t; }" : "=r"(a) : "l"(p));
    return a;
}
#define CPA(s, g) asm volatile("cp.async.cg.shared.global [%0], [%1], 16;" :: "r"(s), "l"(g) : "memory")
#define CPC()     asm volatile("cp.async.commit_group;" ::: "memory")
#define CPW(n)    asm volatile("cp.async.wait_group %0;" :: "n"(n) : "memory")

__device__ __forceinline__ void ldsm4(uint32_t* r, uint32_t a) {
    asm volatile("ldmatrix.sync.aligned.m8n8.x4.shared.b16 {%0,%1,%2,%3}, [%4];"
        : "=r"(r[0]), "=r"(r[1]), "=r"(r[2]), "=r"(r[3]) : "r"(a));
}
__device__ __forceinline__ void ldsm2(uint32_t* r, uint32_t a) {
    asm volatile("ldmatrix.sync.aligned.m8n8.x2.shared.b16 {%0,%1}, [%2];"
        : "=r"(r[0]), "=r"(r[1]) : "r"(a));
}
__device__ __forceinline__ void mma_fp16(float* c, const uint32_t* a, const uint32_t* b) {
    asm volatile("mma.sync.aligned.m16n8k16.row.col.f32.f16.f16.f32 "
        "{%0,%1,%2,%3}, {%4,%5,%6,%7}, {%8,%9}, {%0,%1,%2,%3};"
        : "+f"(c[0]), "+f"(c[1]), "+f"(c[2]), "+f"(c[3])
        : "r"(a[0]), "r"(a[1]), "r"(a[2]), "r"(a[3]), "r"(b[0]), "r"(b[1]));
}
__device__ __forceinline__ void split2h(float x, fp16& h, fp16& l) {
    h = __float2half_rn(x);
    l = __float2half_rn(x - __half2float(h));
}

#define RSB      80
#define TILE_SB  (128 * RSB)     // 10240
#define STAGE_SB (4 * TILE_SB)   // 40960
#define SF_SB    (128 * 80)      // 10240 fp16 E staging (one buffer)
#define DSMEM    (2 * STAGE_SB)                      // 81920
#define DSMEM_F  (2 * STAGE_SB + 2 * SF_SB + 1024)   // 103424

// ===========================================================================
// Merged conv GEMM: grid (32, 2, 12).
// z<4 -> Fq (3-pass, EPI2); z<8 -> G (3-pass, EPI2); z>=8 -> Hv (2-pass, EPI1)
// ===========================================================================
__global__ void __launch_bounds__(256, 2)
conv_merged(const fp16* __restrict__ wfh, const fp16* __restrict__ wfl,
            const fp16* __restrict__ wgh, const fp16* __restrict__ wgl,
            const fp16* __restrict__ whh, const fp16* __restrict__ whl,
            const fp16* __restrict__ FcTh, const fp16* __restrict__ FcTl,
            const fp16* __restrict__ FsTh, const fp16* __restrict__ FsTl,
            const float* __restrict__ b_f, const float* __restrict__ b_g,
            const float* __restrict__ b_h,
            fp16* __restrict__ Fqh, fp16* __restrict__ Fql,
            fp16* __restrict__ Gh,  fp16* __restrict__ Gl,
            fp16* __restrict__ Hvh)
{
    extern __shared__ char smem[];
    const uint32_t sb = smem_u32(smem);
    const int tid = threadIdx.x;
    const int lane = tid & 31, wid = tid >> 5;
    const int wm = wid >> 2, wn = wid & 3;
    const int m0 = blockIdx.y * 128, n0 = blockIdx.x * 128;

    const int zz = blockIdx.z, grp = zz >> 2, b = zz & 3;
    const size_t cn = (size_t)NPIX * CDIM;
    const fp16 *Ah, *Al, *Bh, *Bl;
    const float* bias;
    fp16 *oH, *oL;
    if (grp == 0) {
        Ah = wfh; Al = wfl; Bh = FcTh + b * cn; Bl = FcTl + b * cn;
        bias = b_f; oH = Fqh + b * cn; oL = Fql + b * cn;
    } else if (grp == 1) {
        Ah = wgh; Al = wgl; Bh = FsTh + b * cn; Bl = FsTl + b * cn;
        bias = b_g; oH = Gh + b * cn; oL = Gl + b * cn;
    } else {
        Ah = whh; Al = whl; Bh = FsTh + b * cn; Bl = FsTl + b * cn;
        bias = b_h; oH = Hvh + b * cn; oL = nullptr;
    }
    const bool doP3 = (grp < 2);
    const int epi = (grp < 2) ? 2 : 1;
    const int ldo = (epi == 2) ? CDIM : NPIX;

    const int nk = CDIM / 32;   // 8
    const int r0 = tid >> 2, c0 = tid & 3, r1 = r0 + 64;

    auto issue = [&](int kc) {
        if (kc >= nk) return;
        const uint32_t s0 = sb + (uint32_t)(kc & 1) * STAGE_SB;
        const fp16* srcs[4] = {Ah, Al, Bh, Bl};
#pragma unroll
        for (int t = 0; t < 4; ++t) {
            if (t == 3 && !doP3) continue;
            const fp16* g0 = srcs[t] + (size_t)(r0 + ((t < 2) ? m0 : n0)) * CDIM + kc * 32 + c0 * 8;
            const fp16* g1 = srcs[t] + (size_t)(r1 + ((t < 2) ? m0 : n0)) * CDIM + kc * 32 + c0 * 8;
            CPA(s0 + t * TILE_SB + r0 * RSB + c0 * 16, g0);
            CPA(s0 + t * TILE_SB + r1 * RSB + c0 * 16, g1);
        }
    };

    float acc[4][4][4];
#pragma unroll
    for (int i = 0; i < 4; ++i)
#pragma unroll
        for (int j = 0; j < 4; ++j)
#pragma unroll
            for (int q = 0; q < 4; ++q) acc[i][j][q] = 0.f;

    issue(0); CPC();
    issue(1); CPC();

    const int aRow = lane & 15;
    const int aKB  = (lane >> 4) * 16;
    const int bRow = lane & 7;
    const int bKB  = ((lane >> 3) & 1) * 16;

    for (int kc = 0; kc < nk; ++kc) {
        CPW(1);
        __syncthreads();
        const uint32_t s0 = sb + (uint32_t)(kc & 1) * STAGE_SB;
        const uint32_t aH = s0, aL = s0 + TILE_SB;
        const uint32_t bH = s0 + 2 * TILE_SB, bL = s0 + 3 * TILE_SB;
#pragma unroll
        for (int ks = 0; ks < 2; ++ks) {
            uint32_t Af[2][4][4];
#pragma unroll
            for (int i = 0; i < 4; ++i) {
                const uint32_t off = (uint32_t)(wm * 64 + i * 16 + aRow) * RSB + ks * 32 + aKB;
                ldsm4(Af[0][i], aH + off);
                ldsm4(Af[1][i], aL + off);
            }
#pragma unroll
            for (int jp = 0; jp < 2; ++jp) {
                uint32_t Bf[2][2][2];
#pragma unroll
                for (int jj = 0; jj < 2; ++jj) {
                    const int j = jp * 2 + jj;
                    const uint32_t off = (uint32_t)(wn * 32 + j * 8 + bRow) * RSB + ks * 32 + bKB;
                    ldsm2(Bf[0][jj], bH + off);
                    if (doP3) ldsm2(Bf[1][jj], bL + off);
                }
#pragma unroll
                for (int jj = 0; jj < 2; ++jj)
#pragma unroll
                    for (int i = 0; i < 4; ++i)
                        mma_fp16(acc[i][jp * 2 + jj], Af[0][i], Bf[0][jj]);
#pragma unroll
                for (int jj = 0; jj < 2; ++jj)
#pragma unroll
                    for (int i = 0; i < 4; ++i)
                        mma_fp16(acc[i][jp * 2 + jj], Af[1][i], Bf[0][jj]);
                if (doP3)
#pragma unroll
                    for (int jj = 0; jj < 2; ++jj)
#pragma unroll
                        for (int i = 0; i < 4; ++i)
                            mma_fp16(acc[i][jp * 2 + jj], Af[0][i], Bf[1][jj]);
            }
        }
        __syncthreads();
        issue(kc + 2); CPC();
    }

    // ---- epilogue: stage D (+bias on m) ----
    float* stg = (float*)smem;
    const int gid = lane >> 2, tig = lane & 3;
#pragma unroll
    for (int i = 0; i < 4; ++i) {
        const int ml = wm * 64 + i * 16 + gid;
        const float bv0 = bias[m0 + ml];
        const float bv8 = bias[m0 + ml + 8];
#pragma unroll
        for (int j = 0; j < 4; ++j) {
            const int nl = wn * 32 + j * 8 + tig * 2;
            stg[ml * 132 + nl]           = acc[i][j][0] + bv0;
            stg[ml * 132 + nl + 1]       = acc[i][j][1] + bv0;
            stg[(ml + 8) * 132 + nl]     = acc[i][j][2] + bv8;
            stg[(ml + 8) * 132 + nl + 1] = acc[i][j][3] + bv8;
        }
    }
    __syncthreads();

    const int row = tid >> 1, half = tid & 1;
    if (epi == 2) {
        const int n = row, mh = half * 64;
        const size_t base = (size_t)(n0 + n) * ldo + m0 + mh;
#pragma unroll
        for (int v = 0; v < 8; ++v) {
            uint32_t hw[4], lw[4];
#pragma unroll
            for (int q = 0; q < 4; ++q) {
                float x0 = stg[(mh + v * 8 + q * 2) * 132 + n];
                float x1 = stg[(mh + v * 8 + q * 2 + 1) * 132 + n];
                fp16 h0, l0, h1, l1;
                split2h(x0, h0, l0); split2h(x1, h1, l1);
                __half2 hp = __halves2half2(h0, h1), lp = __halves2half2(l0, l1);
                hw[q] = *(uint32_t*)&hp; lw[q] = *(uint32_t*)&lp;
            }
            *(uint4*)(oH + base + v * 8) = make_uint4(hw[0], hw[1], hw[2], hw[3]);
            *(uint4*)(oL + base + v * 8) = make_uint4(lw[0], lw[1], lw[2], lw[3]);
        }
    } else {
        const size_t base = (size_t)(m0 + row) * ldo + n0 + half * 64;
#pragma unroll
        for (int v = 0; v < 8; ++v) {
            uint32_t hw[4];
#pragma unroll
            for (int q = 0; q < 4; ++q) {
                float x0 = stg[row * 132 + half * 64 + v * 8 + q * 2];
                float x1 = stg[row * 132 + half * 64 + v * 8 + q * 2 + 1];
                __half2 hp = __floats2half2_rn(x0, x1);
                hw[q] = *(uint32_t*)&hp;
            }
            *(uint4*)(oH + base + v * 8) = make_uint4(hw[0], hw[1], hw[2], hw[3]);
        }
    }
}

// ===========================================================================
// Generic GEMM. EPI: 0 fp32(+bias); 2 fp16 transposed; 3 E + stats.
// FUSEB: B from E * exp(mt-m)*il with DOUBLE-BUFFERED E staging; row stats
// computed in-kernel from stM/stS.
// ===========================================================================
template <int EPI, bool FUSEB, int PASSES>
__global__ void __launch_bounds__(256, 2)
mma_gemm(const fp16* __restrict__ Ah_, const fp16* __restrict__ Al_,
         const fp16* __restrict__ Bh_, const fp16* __restrict__ Bl_,
         int K, int lda, int ldb, int ldo,
         long long sA, long long sB, long long sO,
         const float* __restrict__ bias,
         float* __restrict__ outF, fp16* __restrict__ oH, fp16* __restrict__ oL,
         const fp16* __restrict__ Efp,
         const float* __restrict__ stMg, const float* __restrict__ stSg,
         float* __restrict__ stM, float* __restrict__ stS)
{
    extern __shared__ char smem[];
    const uint32_t sb = smem_u32(smem);
    const int tid = threadIdx.x;
    const int lane = tid & 31, wid = tid >> 5;
    const int wm = wid >> 2, wn = wid & 3;
    const int z = blockIdx.z;
    const int m0 = blockIdx.y * 128, n0 = blockIdx.x * 128;

    const fp16* pT[4] = {Ah_ + (size_t)z * sA,
                         (PASSES >= 2) ? Al_ + (size_t)z * sA : nullptr,
                         FUSEB ? nullptr : Bh_ + (size_t)z * sB,
                         (!FUSEB && PASSES >= 3) ? Bl_ + (size_t)z * sB : nullptr};
    const int nk = K / 32;
    const int r0 = tid >> 2, c0 = tid & 3, r1 = r0 + 64;

    auto issueA = [&](int kc) {
        if (kc >= nk) return;
        const uint32_t s0 = sb + (uint32_t)(kc & 1) * STAGE_SB;
#pragma unroll
        for (int t = 0; t < 4; ++t) {
            if (t == 1 && PASSES < 2) continue;
            if (t >= 2 && FUSEB) continue;
            if (t == 3 && PASSES < 3) continue;
            const int ld = (t < 2) ? lda : ldb;
            const int base = (t < 2) ? m0 : n0;
            const fp16* g0 = pT[t] + (size_t)(base + r0) * ld + kc * 32 + c0 * 8;
            const fp16* g1 = pT[t] + (size_t)(base + r1) * ld + kc * 32 + c0 * 8;
            CPA(s0 + t * TILE_SB + r0 * RSB + c0 * 16, g0);
            CPA(s0 + t * TILE_SB + r1 * RSB + c0 * 16, g1);
        }
    };

    const int pr = tid >> 1, jh = tid & 1;
    const uint32_t sf = sb + 2 * STAGE_SB;
    float mrow = 0.f, il = 0.f;
    const fp16* Erow = nullptr;
    float* mS  = (float*)(smem + 2 * STAGE_SB + 2 * SF_SB);
    float* ilS = mS + 128;
    if (FUSEB)
        Erow = Efp + (size_t)z * sB + (size_t)(n0 + pr) * ldb;

    auto issueS = [&](int kc) {     // double-buffered E staging
        if (kc >= nk) return;
        const uint32_t d = sf + (uint32_t)(kc & 1) * SF_SB + pr * 80 + jh * 32;
        const fp16* g = Erow + kc * 32 + jh * 16;
        CPA(d, g); CPA(d + 16, g + 8);
    };
    auto convB = [&](int kc) {
        const uint32_t s0 = sb + (kc & 1) * STAGE_SB;
        const int tile = kc >> 2;
        const float st = stMg[((size_t)z * 32 + tile) * NPIX + (n0 + pr)];
        const float scale = __expf(st - mrow) * il;
        const __half2* Ef = (const __half2*)(smem + 2 * STAGE_SB + (kc & 1) * SF_SB + pr * 80 + jh * 32);
        const uint32_t dH = s0 + 2 * TILE_SB + pr * RSB + jh * 32;
        uint32_t w[8];
#pragma unroll
        for (int q = 0; q < 8; ++q) {
            float2 e = __half22float2(Ef[q]);
            __half2 hp = __floats2half2_rn(e.x * scale, e.y * scale);
            w[q] = *(uint32_t*)&hp;
        }
        asm volatile("st.shared.v4.b32 [%0], {%1,%2,%3,%4};"
            :: "r"(dH), "r"(w[0]), "r"(w[1]), "r"(w[2]), "r"(w[3]) : "memory");
        asm volatile("st.shared.v4.b32 [%0], {%1,%2,%3,%4};"
            :: "r"(dH + 16), "r"(w[4]), "r"(w[5]), "r"(w[6]), "r"(w[7]) : "memory");
    };

    float acc[4][4][4];
#pragma unroll
    for (int i = 0; i < 4; ++i)
#pragma unroll
        for (int j = 0; j < 4; ++j)
#pragma unroll
            for (int q = 0; q < 4; ++q) acc[i][j][q] = 0.f;

    issueA(0); if (FUSEB) issueS(0); CPC();
    issueA(1); if (FUSEB) issueS(1); CPC();

    if (FUSEB) {
        // per-CTA row stats (overlaps the in-flight cp.async groups)
        if (tid < 128) {
            const int irow = n0 + tid;
            float m = -3.0e38f;
#pragma unroll 4
            for (int t = 0; t < 32; ++t)
                m = fmaxf(m, stMg[((size_t)z * 32 + t) * NPIX + irow]);
            float l = 0.f;
#pragma unroll 4
            for (int t = 0; t < 32; ++t) {
                size_t o = ((size_t)z * 32 + t) * NPIX + irow;
                l += stSg[o] * __expf(stMg[o] - m);
            }
            mS[tid] = m; ilS[tid] = 1.0f / l;
        }
        __syncthreads();
        mrow = mS[pr];
        il   = ilS[pr];
    }

    const int aRow = lane & 15;
    const int aKB  = (lane >> 4) * 16;
    const int bRow = lane & 7;
    const int bKB  = ((lane >> 3) & 1) * 16;

    for (int kc = 0; kc < nk; ++kc) {
        CPW(1);
        if (FUSEB) convB(kc);
        __syncthreads();
        const uint32_t s0 = sb + (uint32_t)(kc & 1) * STAGE_SB;
        const uint32_t aH = s0, aL = s0 + TILE_SB;
        const uint32_t bH = s0 + 2 * TILE_SB, bL = s0 + 3 * TILE_SB;
#pragma unroll
        for (int ks = 0; ks < 2; ++ks) {
            uint32_t Af[2][4][4];
#pragma unroll
            for (int i = 0; i < 4; ++i) {
                const uint32_t off = (uint32_t)(wm * 64 + i * 16 + aRow) * RSB + ks * 32 + aKB;
                ldsm4(Af[0][i], aH + off);
                if (PASSES >= 2) ldsm4(Af[1][i], aL + off);
            }
#pragma unroll
            for (int jp = 0; jp < 2; ++jp) {
                uint32_t Bf[2][2][2];
#pragma unroll
                for (int jj = 0; jj < 2; ++jj) {
                    const int j = jp * 2 + jj;
                    const uint32_t off = (uint32_t)(wn * 32 + j * 8 + bRow) * RSB + ks * 32 + bKB;
                    ldsm2(Bf[0][jj], bH + off);
                    if (PASSES >= 3) ldsm2(Bf[1][jj], bL + off);
                }
#pragma unroll
                for (int jj = 0; jj < 2; ++jj)
#pragma unroll
                    for (int i = 0; i < 4; ++i)
                        mma_fp16(acc[i][jp * 2 + jj], Af[0][i], Bf[0][jj]);
                if (PASSES >= 2)
#pragma unroll
                    for (int jj = 0; jj < 2; ++jj)
#pragma unroll
                        for (int i = 0; i < 4; ++i)
                            mma_fp16(acc[i][jp * 2 + jj], Af[1][i], Bf[0][jj]);
                if (PASSES >= 3)
#pragma unroll
                    for (int jj = 0; jj < 2; ++jj)
#pragma unroll
                        for (int i = 0; i < 4; ++i)
                            mma_fp16(acc[i][jp * 2 + jj], Af[0][i], Bf[1][jj]);
            }
        }
        __syncthreads();
        issueA(kc + 2); if (FUSEB) issueS(kc + 2); CPC();
    }

    // ---- epilogue ----
    float* stg = (float*)smem;
    const int gid = lane >> 2, tig = lane & 3;
#pragma unroll
    for (int i = 0; i < 4; ++i) {
        const int ml = wm * 64 + i * 16 + gid;
        const float bv0 = bias ? bias[m0 + ml] : 0.f;
        const float bv8 = bias ? bias[m0 + ml + 8] : 0.f;
#pragma unroll
        for (int j = 0; j < 4; ++j) {
            const int nl = wn * 32 + j * 8 + tig * 2;
            stg[ml * 132 + nl]           = acc[i][j][0] + bv0;
            stg[ml * 132 + nl + 1]       = acc[i][j][1] + bv0;
            stg[(ml + 8) * 132 + nl]     = acc[i][j][2] + bv8;
            stg[(ml + 8) * 132 + nl + 1] = acc[i][j][3] + bv8;
        }
    }
    __syncthreads();

    const int row = tid >> 1, half = tid & 1;
    if (EPI == 0) {
        float* dst = outF + (size_t)z * sO + (size_t)(m0 + row) * ldo + n0 + half * 64;
        const float4* s4 = (const float4*)&stg[row * 132 + half * 64];
#pragma unroll
        for (int i = 0; i < 16; ++i) ((float4*)dst)[i] = s4[i];
    } else if (EPI == 2) {
        const int n = row, mh = half * 64;
        const size_t base = (size_t)z * sO + (size_t)(n0 + n) * ldo + m0 + mh;
#pragma unroll
        for (int v = 0; v < 8; ++v) {
            uint32_t hw[4];
#pragma unroll
            for (int q = 0; q < 4; ++q) {
                float x0 = stg[(mh + v * 8 + q * 2) * 132 + n];
                float x1 = stg[(mh + v * 8 + q * 2 + 1) * 132 + n];
                __half2 hp = __floats2half2_rn(x0, x1);
                hw[q] = *(uint32_t*)&hp;
            }
            *(uint4*)(oH + base + v * 8) = make_uint4(hw[0], hw[1], hw[2], hw[3]);
        }
    } else {   // EPI == 3
        const size_t base = (size_t)z * sO + (size_t)(m0 + row) * ldo + n0 + half * 64;
        const float* src = &stg[row * 132 + half * 64];
        float mx = -3.0e38f;
#pragma unroll
        for (int q = 0; q < 64; ++q) mx = fmaxf(mx, src[q]);
        mx = fmaxf(mx, __shfl_xor_sync(0xffffffffu, mx, 1));
        float s = 0.f;
#pragma unroll
        for (int v = 0; v < 8; ++v) {
            uint32_t w[4];
#pragma unroll
            for (int q = 0; q < 4; ++q) {
                float e0 = __expf(src[v * 8 + q * 2]     - mx);
                float e1 = __expf(src[v * 8 + q * 2 + 1] - mx);
                s += e0 + e1;
                __half2 hp = __floats2half2_rn(e0, e1);
                w[q] = *(uint32_t*)&hp;
            }
            *(uint4*)(oH + base + v * 8) = make_uint4(w[0], w[1], w[2], w[3]);
        }
        s += __shfl_xor_sync(0xffffffffu, s, 1);
        if (half == 0) {
            size_t o = ((size_t)z * 32 + blockIdx.x) * NPIX + m0 + row;
            stM[o] = mx; stS[o] = s;
        }
    }
}

// ---------------------------------------------------------------------------
// fp32 [b][c][p] -> fp16 hi/lo transposed [b][p][c] (vectorized writes)
// ---------------------------------------------------------------------------
__global__ void __launch_bounds__(256)
tsplit_both(const float* __restrict__ Fc, const float* __restrict__ Fs,
            fp16* __restrict__ ohc, fp16* __restrict__ olc,
            fp16* __restrict__ ohs, fp16* __restrict__ ols)
{
    __shared__ float t[32][65];   // [p][c]
    const int zz = blockIdx.z;
    const int b = zz & 3;
    const float* X = (zz < 4) ? Fc : Fs;
    fp16* oh = (zz < 4) ? ohc : ohs;
    fp16* ol = (zz < 4) ? olc : ols;
    const int pb = blockIdx.x * 32, cb = blockIdx.y * 64;
    const float* src = X + (size_t)b * CDIM * NPIX;
    const int tid = threadIdx.x;

    const int lp = tid & 31, lc = tid >> 5;
#pragma unroll
    for (int it = 0; it < 8; ++it) {
        const int c = lc + it * 8;
        t[lp][c] = src[(size_t)(cb + c) * NPIX + pb + lp];
    }
    __syncthreads();

    const int wpair = tid & 31, wp = tid >> 5;
#pragma unroll
    for (int it = 0; it < 4; ++it) {
        const int p = wp + it * 8;
        const float x0 = t[p][wpair * 2];
        const float x1 = t[p][wpair * 2 + 1];
        fp16 h0, l0, h1, l1;
        split2h(x0, h0, l0); split2h(x1, h1, l1);
        __half2 hp = __halves2half2(h0, h1), lpk = __halves2half2(l0, l1);
        const size_t o = (size_t)b * NPIX * CDIM + (size_t)(pb + p) * CDIM + cb + wpair * 2;
        *(__half2*)(oh + o) = hp;
        *(__half2*)(ol + o) = lpk;
    }
}

__global__ void __launch_bounds__(256)
wsplit_all(const float* __restrict__ w0, const float* __restrict__ w1,
           const float* __restrict__ w2, const float* __restrict__ w3,
           fp16* __restrict__ h0, fp16* __restrict__ l0,
           fp16* __restrict__ h1, fp16* __restrict__ l1,
           fp16* __restrict__ h2, fp16* __restrict__ l2,
           fp16* __restrict__ h3, fp16* __restrict__ l3)
{
    const float* w = (blockIdx.y == 0) ? w0 : (blockIdx.y == 1) ? w1 : (blockIdx.y == 2) ? w2 : w3;
    fp16* hh = (blockIdx.y == 0) ? h0 : (blockIdx.y == 1) ? h1 : (blockIdx.y == 2) ? h2 : h3;
    fp16* ll = (blockIdx.y == 0) ? l0 : (blockIdx.y == 1) ? l1 : (blockIdx.y == 2) ? l2 : l3;
    int i = (blockIdx.x * 256 + threadIdx.x) * 2;
    if (i < CDIM * CDIM) {
        float2 v = *(const float2*)(w + i);
        fp16 a0, b0, a1, b1;
        split2h(v.x, a0, b0); split2h(v.y, a1, b1);
        *(__half2*)(hh + i) = __halves2half2(a0, a1);
        *(__half2*)(ll + i) = __halves2half2(b0, b1);
    }
}

// ---------------------------------------------------------------------------
extern "C" void kernel_launch(void* const* d_in, const int* in_sizes, int n_in,
                              void* d_out, int out_size)
{
    const float* F_c = (const float*)d_in[0];
    const float* F_s = (const float*)d_in[1];
    const float* w_f = (const float*)d_in[2];
    const float* b_f = (const float*)d_in[3];
    const float* w_g = (const float*)d_in[4];
    const float* b_g = (const float*)d_in[5];
    const float* w_h = (const float*)d_in[6];
    const float* b_h = (const float*)d_in[7];
    const float* w_o = (const float*)d_in[8];
    const float* b_o = (const float*)d_in[9];
    float* out = (float*)d_out;

    fp16 *FcTh, *FcTl, *FsTh, *FsTl, *wfh, *wfl, *wgh, *wgl, *whh, *whl, *woh, *wol;
    fp16 *Fqh, *Fql, *Gh, *Gl, *Hvh, *Rh, *E;
    float *stM, *stS;
    cudaGetSymbolAddress((void**)&FcTh, g_FcT_h); cudaGetSymbolAddress((void**)&FcTl, g_FcT_l);
    cudaGetSymbolAddress((void**)&FsTh, g_FsT_h); cudaGetSymbolAddress((void**)&FsTl, g_FsT_l);
    cudaGetSymbolAddress((void**)&wfh, g_wf_h);   cudaGetSymbolAddress((void**)&wfl, g_wf_l);
    cudaGetSymbolAddress((void**)&wgh, g_wg_h);   cudaGetSymbolAddress((void**)&wgl, g_wg_l);
    cudaGetSymbolAddress((void**)&whh, g_wh_h);   cudaGetSymbolAddress((void**)&whl, g_wh_l);
    cudaGetSymbolAddress((void**)&woh, g_wo_h);   cudaGetSymbolAddress((void**)&wol, g_wo_l);
    cudaGetSymbolAddress((void**)&Fqh, g_Fq_h);   cudaGetSymbolAddress((void**)&Fql, g_Fq_l);
    cudaGetSymbolAddress((void**)&Gh,  g_G_h);    cudaGetSymbolAddress((void**)&Gl,  g_G_l);
    cudaGetSymbolAddress((void**)&Hvh, g_Hv_h);   cudaGetSymbolAddress((void**)&Rh,  g_R_h);
    cudaGetSymbolAddress((void**)&E,   g_E);
    cudaGetSymbolAddress((void**)&stM, g_stM);    cudaGetSymbolAddress((void**)&stS, g_stS);

    cudaFuncSetAttribute((const void*)conv_merged, cudaFuncAttributeMaxDynamicSharedMemorySize, DSMEM);
    cudaFuncSetAttribute((const void*)mma_gemm<3,false,3>, cudaFuncAttributeMaxDynamicSharedMemorySize, DSMEM);
    cudaFuncSetAttribute((const void*)mma_gemm<2,true ,1>, cudaFuncAttributeMaxDynamicSharedMemorySize, DSMEM_F);
    cudaFuncSetAttribute((const void*)mma_gemm<0,false,2>, cudaFuncAttributeMaxDynamicSharedMemorySize, DSMEM);

    const long long cn = (long long)NPIX * CDIM;
    const long long nn = (long long)NPIX * NPIX;

    dim3 gConv(NPIX / 128, CDIM / 128, BATCH);     // 32 x 2 x 4
    dim3 gConvM(NPIX / 128, CDIM / 128, 3 * BATCH);// 32 x 2 x 12
    dim3 gS(NPIX / 128, NPIX / 128, BATCH);        // 32 x 32 x 4

    // L1, L2: conversions
    wsplit_all<<<dim3(128, 4), 256>>>(w_f, w_g, w_h, w_o,
        wfh, wfl, wgh, wgl, whh, whl, woh, wol);
    tsplit_both<<<dim3(NPIX / 32, CDIM / 64, 8), 256>>>(F_c, F_s, FcTh, FcTl, FsTh, FsTl);
    // L3: merged G1+G2+G3 (Hv 2-pass)
    conv_merged<<<gConvM, 256, DSMEM>>>(wfh, wfl, wgh, wgl, whh, whl,
        FcTh, FcTl, FsTh, FsTl, b_f, b_g, b_h, Fqh, Fql, Gh, Gl, Hvh);
    // L4 (G4): E + stats (3-pass)
    mma_gemm<3,false,3><<<gS, 256, DSMEM>>>(Fqh, Fql, Gh, Gl,
        CDIM, CDIM, CDIM, NPIX, cn, cn, nn, nullptr, nullptr, E, nullptr,
        nullptr, nullptr, nullptr, stM, stS);
    // L5 (G5): R_t hi only (1-pass, FUSEB, double-buffered E staging)
    mma_gemm<2,true,1><<<gConv, 256, DSMEM_F>>>(Hvh, nullptr, nullptr, nullptr,
        NPIX, NPIX, NPIX, CDIM, cn, nn, cn, nullptr, nullptr, Rh, nullptr,
        E, stM, stS, nullptr, nullptr);
    // L6 (G6): out = w_o @ R + b_o (2-pass)
    mma_gemm<0,false,2><<<gConv, 256, DSMEM>>>(woh, wol, Rh, nullptr,
        CDIM, CDIM, CDIM, NPIX, 0, cn, cn, b_o, out, nullptr, nullptr,
        nullptr, nullptr, nullptr, nullptr, nullptr);
}